// round 3
// baseline (speedup 1.0000x reference)
#include <cuda_runtime.h>
#include <math.h>

typedef unsigned long long ull;

// ---------------------------------------------------------------------------
// EfficientVSR windowed cross-attention, fully fused, f32x2-packed math.
// One CTA (512 thr) per 8x8 window. B=8, C=128, H=W=256, heads=4, hd=32.
// ---------------------------------------------------------------------------

constexpr int TPB   = 512;
constexpr int CH    = 128;
constexpr int IMG_H = 256;
constexpr int IMG_W = 256;
constexpr int WSZ   = 8;
constexpr int NTOK  = 64;
constexpr int XP    = 132;   // row stride (floats) for 64x128 row-major tiles

// smem layout (float offsets)
constexpr int OFF_Q  = 0;                    // Q (row-major), later final out    8448
constexpr int OFF_KT = 8448;                 // Kt2[c/2][m][2]   64*128 = 8192
constexpr int OFF_V2 = 16640;                // V2[m/2][c][2]    32*256 = 8192
constexpr int OFF_P  = 24832;                // spatial in, later attn out  8448
constexpr int OFF_WT = 33280;                // staged weight tile 16*256 = 4096
constexpr int OFF_S  = 37376;                // scores 4*64*68 = 17408; also temporal staging / residual
constexpr int OFF_LN = 54784;                // ln_w(128) + ln_b(128)
constexpr int SMEM_FLOATS = 55040;
constexpr int SMEM_BYTES  = SMEM_FLOATS * 4; // 220160 B

// pre-transformed weights: WTg[m][(c>>1)*256 + d*2 + (c&1)] = W_m[d][c]
__device__ __align__(16) float WTg[4 * 128 * 128];

__device__ __forceinline__ ull ffma2(ull a, ull b, ull c) {
    ull d;
    asm("fma.rn.f32x2 %0, %1, %2, %3;" : "=l"(d) : "l"(a), "l"(b), "l"(c));
    return d;
}
__device__ __forceinline__ float f2sum(ull p) {
    float lo = __uint_as_float((unsigned)(p & 0xffffffffu));
    float hi = __uint_as_float((unsigned)(p >> 32));
    return lo + hi;
}

// weight transpose + k-pair interleave (tiny, once per launch)
__global__ void __launch_bounds__(256) prep_kernel(
    const float* __restrict__ Wq, const float* __restrict__ Wk,
    const float* __restrict__ Wv, const float* __restrict__ Wo)
{
    int m = blockIdx.y;
    const float* Ws = (m == 0) ? Wq : (m == 1) ? Wk : (m == 2) ? Wv : Wo;
    int idx = blockIdx.x * 256 + threadIdx.x;   // 0..16383
    int d = idx >> 7, c = idx & 127;
    WTg[m * 16384 + (c >> 1) * 256 + d * 2 + (c & 1)] = Ws[d * 128 + c];
}

// out[t][d] = sum_c X[t][c]*W[d][c]; X row-major at srcOff (stride XP).
// mode 0: row-major to dstOff; mode 1: Kt2; mode 2: V2.
__device__ __forceinline__ void gemm_proj(
    float* sm, int srcOff, const float* __restrict__ wglob,
    int mode, int dstOff, int tid)
{
    const int lane = tid & 31;
    const int w    = tid >> 5;
    const int rb   = ((w >> 3) << 5) + (lane >> 2); // thread rows rb + 8*i
    const int c0   = ((w & 7) << 4) + ((lane & 3) << 2);

    ull acc[4][4];
#pragma unroll
    for (int i = 0; i < 4; i++)
#pragma unroll
        for (int j = 0; j < 4; j++) acc[i][j] = 0ULL;

    for (int k0 = 0; k0 < CH; k0 += 32) {
        // stage 32 k-values (16 k-pair rows x 256 floats) — flat float4 copy
#pragma unroll
        for (int j = 0; j < 2; j++) {
            int i = tid + j * TPB;
            ((float4*)(sm + OFF_WT))[i] = ((const float4*)wglob)[(k0 << 5) + i];
        }
        __syncthreads();

#pragma unroll 4
        for (int p = 0; p < 16; p++) {
            const float* xb = sm + srcOff + rb * XP + k0 + 2 * p;
            ull x0 = *(const ull*)(xb);
            ull x1 = *(const ull*)(xb + 8 * XP);
            ull x2 = *(const ull*)(xb + 16 * XP);
            ull x3 = *(const ull*)(xb + 24 * XP);
            const ulonglong2* wp = (const ulonglong2*)(sm + OFF_WT + p * 256 + c0 * 2);
            ulonglong2 wa = wp[0], wb = wp[1];
            ull w0 = wa.x, w1 = wa.y, w2 = wb.x, w3 = wb.y;
            acc[0][0] = ffma2(x0, w0, acc[0][0]); acc[0][1] = ffma2(x0, w1, acc[0][1]);
            acc[0][2] = ffma2(x0, w2, acc[0][2]); acc[0][3] = ffma2(x0, w3, acc[0][3]);
            acc[1][0] = ffma2(x1, w0, acc[1][0]); acc[1][1] = ffma2(x1, w1, acc[1][1]);
            acc[1][2] = ffma2(x1, w2, acc[1][2]); acc[1][3] = ffma2(x1, w3, acc[1][3]);
            acc[2][0] = ffma2(x2, w0, acc[2][0]); acc[2][1] = ffma2(x2, w1, acc[2][1]);
            acc[2][2] = ffma2(x2, w2, acc[2][2]); acc[2][3] = ffma2(x2, w3, acc[2][3]);
            acc[3][0] = ffma2(x3, w0, acc[3][0]); acc[3][1] = ffma2(x3, w1, acc[3][1]);
            acc[3][2] = ffma2(x3, w2, acc[3][2]); acc[3][3] = ffma2(x3, w3, acc[3][3]);
        }
        __syncthreads();
    }

    if (mode == 0) {
#pragma unroll
        for (int i = 0; i < 4; i++) {
            int r = rb + 8 * i;
            float4 o;
            o.x = f2sum(acc[i][0]); o.y = f2sum(acc[i][1]);
            o.z = f2sum(acc[i][2]); o.w = f2sum(acc[i][3]);
            *(float4*)&sm[dstOff + r * XP + c0] = o;
        }
    } else if (mode == 1) { // Kt2[c>>1][t][c&1]
#pragma unroll
        for (int i = 0; i < 4; i++) {
            int r = rb + 8 * i;
#pragma unroll
            for (int j = 0; j < 4; j++) {
                int c = c0 + j;
                sm[OFF_KT + ((c >> 1) << 7) + r * 2 + (c & 1)] = f2sum(acc[i][j]);
            }
        }
    } else {                // V2[t>>1][c][t&1]
#pragma unroll
        for (int i = 0; i < 4; i++) {
            int r = rb + 8 * i;
#pragma unroll
            for (int j = 0; j < 4; j++)
                sm[OFF_V2 + ((r >> 1) << 8) + (c0 + j) * 2 + (r & 1)] = f2sum(acc[i][j]);
        }
    }
}

__global__ void __launch_bounds__(TPB, 1)
evsr_kernel(const float* __restrict__ tf, const float* __restrict__ sf,
            const float* __restrict__ lnw, const float* __restrict__ lnb,
            float* __restrict__ out)
{
    extern __shared__ float sm[];
    const int tid = threadIdx.x;
    const int blk = blockIdx.x;
    const int b   = blk >> 10;
    const int wy  = (blk >> 5) & 31;
    const int wx  = blk & 31;
    const int base = ((b * CH) << 16) + ((wy * WSZ) << 8) + (wx * WSZ);

    // ---- Phase 1: temporal -> S region, spatial -> P; ln params -> smem ----
#pragma unroll
    for (int k = 0; k < 16; k++) {
        int idx = tid + k * TPB;
        int c = idx >> 6;
        int t = idx & 63;
        int g = base + (c << 16) + ((t >> 3) << 8) + (t & 7);
        sm[OFF_S + t * XP + c] = tf[g];
        sm[OFF_P + t * XP + c] = sf[g];
    }
    if (tid < 256) sm[OFF_LN + tid] = (tid < 128) ? lnw[tid] : lnb[tid - 128];
    __syncthreads();

    // ---- Phase 2: projections ----
    gemm_proj(sm, OFF_S, WTg,          0, OFF_Q, tid);   // Q (row-major)
    gemm_proj(sm, OFF_P, WTg + 16384,  1, 0,     tid);   // K -> Kt2
    gemm_proj(sm, OFF_P, WTg + 32768,  2, 0,     tid);   // V -> V2
    __syncthreads();

    // ---- Phase 3: 2D RoPE on Q (row-major) and K (Kt2 layout) ----
#pragma unroll
    for (int k = 0; k < 8; k++) {
        int idx = tid + k * TPB;           // 4096 = 64t * 4h * 16i
        int t = idx >> 6;
        int h = (idx >> 4) & 3;
        int i = idx & 15;
        float freq = exp2f(-(float)i * 0.830482023721841f); // 10000^(-i/16)
        float ang = (float)((t >> 3) + (t & 7)) * freq;
        float sv, cv;
        __sincosf(ang, &sv, &cv);
        int c1 = h * 32 + i;
        int c2 = c1 + 16;
        float q1 = sm[OFF_Q + t * XP + c1], q2 = sm[OFF_Q + t * XP + c2];
        sm[OFF_Q + t * XP + c1] = q1 * cv - q2 * sv;
        sm[OFF_Q + t * XP + c2] = q1 * sv + q2 * cv;
        int a1 = OFF_KT + ((c1 >> 1) << 7) + t * 2 + (c1 & 1);
        int a2 = OFF_KT + ((c2 >> 1) << 7) + t * 2 + (c2 & 1);
        float k1 = sm[a1], k2 = sm[a2];
        sm[a1] = k1 * cv - k2 * sv;
        sm[a2] = k1 * sv + k2 * cv;
    }
    __syncthreads();

    // ---- Phase 4a: S = Q K^T * scale (all 4 heads) ----
    {
        const int h  = tid >> 7;
        const int t7 = tid & 127;
        const int q0 = (t7 >> 3) << 2;     // 4 q rows
        const int m0 = (t7 & 7) << 3;      // 8 m cols
        ull acc[4][8];
#pragma unroll
        for (int i = 0; i < 4; i++)
#pragma unroll
            for (int j = 0; j < 8; j++) acc[i][j] = 0ULL;

        const ull* ktp = (const ull*)(sm + OFF_KT);
#pragma unroll 4
        for (int k2 = 0; k2 < 16; k2++) {
            const float* qb = sm + OFF_Q + q0 * XP + h * 32 + 2 * k2;
            ull q0v = *(const ull*)(qb);
            ull q1v = *(const ull*)(qb + XP);
            ull q2v = *(const ull*)(qb + 2 * XP);
            ull q3v = *(const ull*)(qb + 3 * XP);
            const ulonglong2* kp = (const ulonglong2*)(ktp + ((h * 16 + k2) << 6) + m0);
            ulonglong2 ka = kp[0], kb = kp[1], kc = kp[2], kd = kp[3];
            ull km[8] = {ka.x, ka.y, kb.x, kb.y, kc.x, kc.y, kd.x, kd.y};
#pragma unroll
            for (int j = 0; j < 8; j++) {
                acc[0][j] = ffma2(q0v, km[j], acc[0][j]);
                acc[1][j] = ffma2(q1v, km[j], acc[1][j]);
                acc[2][j] = ffma2(q2v, km[j], acc[2][j]);
                acc[3][j] = ffma2(q3v, km[j], acc[3][j]);
            }
        }
        const float scale = 0.17677669529663687f;
#pragma unroll
        for (int i = 0; i < 4; i++) {
            float* sr = sm + OFF_S + (h * 64 + q0 + i) * 68 + m0;
            float4 oa, ob;
            oa.x = f2sum(acc[i][0]) * scale; oa.y = f2sum(acc[i][1]) * scale;
            oa.z = f2sum(acc[i][2]) * scale; oa.w = f2sum(acc[i][3]) * scale;
            ob.x = f2sum(acc[i][4]) * scale; ob.y = f2sum(acc[i][5]) * scale;
            ob.z = f2sum(acc[i][6]) * scale; ob.w = f2sum(acc[i][7]) * scale;
            *(float4*)(sr)     = oa;
            *(float4*)(sr + 4) = ob;
        }
    }
    __syncthreads();

    // ---- Phase 4b: softmax, 2 threads per row ----
    {
        int rid = tid >> 1, half = tid & 1;
        float* row = sm + OFF_S + rid * 68 + half * 32;
        float mx = -1e30f;
#pragma unroll 8
        for (int j = 0; j < 32; j++) mx = fmaxf(mx, row[j]);
        mx = fmaxf(mx, __shfl_xor_sync(0xffffffffu, mx, 1));
        float s = 0.0f;
#pragma unroll 8
        for (int j = 0; j < 32; j++) {
            float e = __expf(row[j] - mx);
            row[j] = e;
            s += e;
        }
        s += __shfl_xor_sync(0xffffffffu, s, 1);
        float inv = 1.0f / s;
#pragma unroll 8
        for (int j = 0; j < 32; j++) row[j] *= inv;
    }
    __syncthreads();

    // ---- Phase 4c: O = S V (all heads) -> P ----
    {
        const int lane = tid & 31;
        const int w    = tid >> 5;
        const int rb   = ((w >> 3) << 5) + (lane >> 2);
        const int c0   = ((w & 7) << 4) + ((lane & 3) << 2);
        const int h    = c0 >> 5;
        ull acc[4][4];
#pragma unroll
        for (int i = 0; i < 4; i++)
#pragma unroll
            for (int j = 0; j < 4; j++) acc[i][j] = 0ULL;

        const ull* vp = (const ull*)(sm + OFF_V2);
        const float* sb = sm + OFF_S + (h * 64 + rb) * 68;
#pragma unroll 4
        for (int m2 = 0; m2 < 32; m2++) {
            ull s0 = *(const ull*)(sb + 2 * m2);
            ull s1 = *(const ull*)(sb + 8 * 68 + 2 * m2);
            ull s2 = *(const ull*)(sb + 16 * 68 + 2 * m2);
            ull s3 = *(const ull*)(sb + 24 * 68 + 2 * m2);
            const ulonglong2* vv = (const ulonglong2*)(vp + (m2 << 7) + c0);
            ulonglong2 va = vv[0], vb = vv[1];
            ull v0 = va.x, v1 = va.y, v2 = vb.x, v3 = vb.y;
            acc[0][0] = ffma2(s0, v0, acc[0][0]); acc[0][1] = ffma2(s0, v1, acc[0][1]);
            acc[0][2] = ffma2(s0, v2, acc[0][2]); acc[0][3] = ffma2(s0, v3, acc[0][3]);
            acc[1][0] = ffma2(s1, v0, acc[1][0]); acc[1][1] = ffma2(s1, v1, acc[1][1]);
            acc[1][2] = ffma2(s1, v2, acc[1][2]); acc[1][3] = ffma2(s1, v3, acc[1][3]);
            acc[2][0] = ffma2(s2, v0, acc[2][0]); acc[2][1] = ffma2(s2, v1, acc[2][1]);
            acc[2][2] = ffma2(s2, v2, acc[2][2]); acc[2][3] = ffma2(s2, v3, acc[2][3]);
            acc[3][0] = ffma2(s3, v0, acc[3][0]); acc[3][1] = ffma2(s3, v1, acc[3][1]);
            acc[3][2] = ffma2(s3, v2, acc[3][2]); acc[3][3] = ffma2(s3, v3, acc[3][3]);
        }
#pragma unroll
        for (int i = 0; i < 4; i++) {
            int r = rb + 8 * i;
            float4 o;
            o.x = f2sum(acc[i][0]); o.y = f2sum(acc[i][1]);
            o.z = f2sum(acc[i][2]); o.w = f2sum(acc[i][3]);
            *(float4*)&sm[OFF_P + r * XP + c0] = o;
        }
    }
    __syncthreads();

    // ---- Phase 5: reload temporal residual into S region (overlaps Wo GEMM) ----
#pragma unroll
    for (int k = 0; k < 16; k++) {
        int idx = tid + k * TPB;
        int c = idx >> 6;
        int t = idx & 63;
        sm[OFF_S + t * XP + c] = tf[base + (c << 16) + ((t >> 3) << 8) + (t & 7)];
    }

    // ---- Phase 6: output projection -> Q region ----
    gemm_proj(sm, OFF_P, WTg + 49152, 0, OFF_Q, tid);
    __syncthreads();

    // ---- Phase 7: LayerNorm + residual, 8 threads per token ----
    {
        int t = tid >> 3, j = tid & 7;
        float* xr = sm + OFF_Q + t * XP + j * 16;
        float s1 = 0.0f, s2 = 0.0f;
#pragma unroll
        for (int g = 0; g < 4; g++) {
            float4 v = ((float4*)xr)[g];
            s1 += v.x + v.y + v.z + v.w;
            s2 += v.x * v.x + v.y * v.y + v.z * v.z + v.w * v.w;
        }
#pragma unroll
        for (int d = 1; d < 8; d <<= 1) {
            s1 += __shfl_xor_sync(0xffffffffu, s1, d, 8);
            s2 += __shfl_xor_sync(0xffffffffu, s2, d, 8);
        }
        float mu  = s1 * (1.0f / 128.0f);
        float var = s2 * (1.0f / 128.0f) - mu * mu;
        float inv = rsqrtf(var + 1e-5f);
        const float* resid = sm + OFF_S  + t * XP + j * 16;
        const float* lw    = sm + OFF_LN + j * 16;
        const float* lb    = sm + OFF_LN + 128 + j * 16;
#pragma unroll
        for (int c = 0; c < 16; c++)
            xr[c] = (xr[c] - mu) * inv * lw[c] + lb[c] + resid[c];
    }
    __syncthreads();

    // ---- Phase 8: store ----
#pragma unroll
    for (int k = 0; k < 16; k++) {
        int idx = tid + k * TPB;
        int c = idx >> 6;
        int t = idx & 63;
        out[base + (c << 16) + ((t >> 3) << 8) + (t & 7)] = sm[OFF_Q + t * XP + c];
    }
}

extern "C" void kernel_launch(void* const* d_in, const int* in_sizes, int n_in,
                              void* d_out, int out_size)
{
    const float* tf  = (const float*)d_in[0];
    const float* sf  = (const float*)d_in[1];
    const float* Wq  = (const float*)d_in[2];
    const float* Wk  = (const float*)d_in[3];
    const float* Wv  = (const float*)d_in[4];
    const float* Wo  = (const float*)d_in[5];
    const float* lnw = (const float*)d_in[6];
    const float* lnb = (const float*)d_in[7];
    float* out = (float*)d_out;

    int B = in_sizes[0] / (CH * IMG_H * IMG_W);
    int n_windows = B * (IMG_H / WSZ) * (IMG_W / WSZ);

    dim3 pg(64, 4);
    prep_kernel<<<pg, 256>>>(Wq, Wk, Wv, Wo);

    cudaFuncSetAttribute(evsr_kernel, cudaFuncAttributeMaxDynamicSharedMemorySize,
                         SMEM_BYTES);
    evsr_kernel<<<n_windows, TPB, SMEM_BYTES>>>(tf, sf, lnw, lnb, out);
}

// round 9
// speedup vs baseline: 1.5144x; 1.5144x over previous
#include <cuda_runtime.h>
#include <cuda_bf16.h>
#include <mma.h>
#include <math.h>

using namespace nvcuda;
typedef __nv_bfloat16 bf16;

// ---------------------------------------------------------------------------
// EfficientVSR windowed cross-attention, fused, WMMA bf16 (m16n16k16) with
// hi/lo 3-term compensation. One CTA (256 thr, 8 warps) per 8x8 window.
// B=8, C=128, H=W=256, heads=4, hd=32.
// ---------------------------------------------------------------------------

constexpr int TPB   = 256;
constexpr int CH    = 128;
constexpr int IMG_H = 256;
constexpr int IMG_W = 256;
constexpr int WSZ   = 8;

constexpr int XS_H = 136;   // half stride for 64x128 bf16 tiles (mult of 8)
constexpr int WS_H = 40;    // weight slab half stride (32 + 8 pad)
constexpr int PS_H = 72;    // probs half stride
constexpr int F0S  = 132;   // F0 float stride for 128-wide
constexpr int SS   = 68;    // S strip float stride
constexpr int F1S  = 132;   // F1 float stride

// smem byte offsets
constexpr int OFF_XQ = 0;        // XQ hi/lo -> later Q hi/lo       34816
constexpr int OFF_XS = 34816;    // XS hi/lo -> later V hi/lo       34816
constexpr int OFF_KA = 69632;    // K hi/lo  -> later AO hi/lo      34816
constexpr int OFF_WS = 104448;   // weight slab hi/lo               20480
constexpr int OFF_P  = 124928;   // probs hi/lo, 2 head strips      36864
constexpr int OFF_F0 = 161792;   // fp32 scratch (proj out / S)     34816
constexpr int OFF_F1 = 196608;   // fp32 scratch (AO / residual)    33792
constexpr int OFF_LN = 230400;   // ln_w + ln_b                      1024
constexpr int SMEM_BYTES = 231424;

constexpr int HL = 8704;   // half offset hi->lo within XQ/XS/KA regions (64*136)
constexpr int WSL = 5120;  // half offset hi->lo within weight slab (128*40)
constexpr int PH = 4608;   // halves per P buffer (64*72)

// prepped weights: plain [m][d][c] bf16 hi and lo
__device__ __align__(16) bf16 WHg[4 * 16384];
__device__ __align__(16) bf16 WLg[4 * 16384];

__device__ __forceinline__ void split_bf(float v, bf16& h, bf16& l) {
    h = __float2bfloat16_rn(v);
    l = __float2bfloat16_rn(v - __bfloat162float(h));
}

__global__ void __launch_bounds__(256) prep_kernel(
    const float* __restrict__ Wq, const float* __restrict__ Wk,
    const float* __restrict__ Wv, const float* __restrict__ Wo)
{
    int m = blockIdx.y;
    const float* Ws = (m == 0) ? Wq : (m == 1) ? Wk : (m == 2) ? Wv : Wo;
    int idx = blockIdx.x * 256 + threadIdx.x;   // 0..16383
    bf16 h, l;
    split_bf(Ws[idx], h, l);
    WHg[m * 16384 + idx] = h;
    WLg[m * 16384 + idx] = l;
}

typedef wmma::fragment<wmma::matrix_a, 16, 16, 16, bf16, wmma::row_major> FragA;
typedef wmma::fragment<wmma::matrix_b, 16, 16, 16, bf16, wmma::col_major> FragBc;
typedef wmma::fragment<wmma::matrix_b, 16, 16, 16, bf16, wmma::row_major> FragBr;
typedef wmma::fragment<wmma::accumulator, 16, 16, 16, float> FragC;

// D[64,128] = A[64,128] @ W_m^T, A = hi/lo bf16 at Ah (lo at +HL), stride XS_H.
// D fp32 at Df, stride F0S. Weight staged in 32-wide k slabs.
__device__ __forceinline__ void proj_wmma(char* smem, const bf16* Ah, int widx,
                                          float* Df, int tid)
{
    const int w  = tid >> 5;
    const int mt = w & 3;        // m tile (16 rows)
    const int nh = w >> 2;       // n half (4 n-tiles each)
    bf16* WSh = (bf16*)(smem + OFF_WS);

    FragC acc[4];
#pragma unroll
    for (int j = 0; j < 4; j++) wmma::fill_fragment(acc[j], 0.0f);

    const unsigned* srcH = (const unsigned*)(WHg + widx * 16384);
    const unsigned* srcL = (const unsigned*)(WLg + widx * 16384);
    unsigned* dstH = (unsigned*)WSh;            // stride 20 uint (40 halves)
    unsigned* dstL = (unsigned*)(WSh + WSL);

#pragma unroll
    for (int s = 0; s < 4; s++) {
        // stage slab: W[d][s*32 .. s*32+32) hi+lo. 2048 uint each.
#pragma unroll
        for (int j = 0; j < 8; j++) {
            int u = tid + j * TPB;              // 0..2047
            int d = u >> 4, cp = u & 15;
            dstH[d * 20 + cp] = srcH[d * 64 + s * 16 + cp];
            dstL[d * 20 + cp] = srcL[d * 64 + s * 16 + cp];
        }
        __syncthreads();

#pragma unroll
        for (int ktl = 0; ktl < 2; ktl++) {
            const int k0 = ktl * 16;
            FragA aH, aL;
            wmma::load_matrix_sync(aH, Ah + (mt * 16) * XS_H + s * 32 + k0, XS_H);
            wmma::load_matrix_sync(aL, Ah + HL + (mt * 16) * XS_H + s * 32 + k0, XS_H);
#pragma unroll
            for (int j = 0; j < 4; j++) {
                const int nt = nh * 4 + j;
                FragBc bH, bL;
                wmma::load_matrix_sync(bH, WSh + (nt * 16) * WS_H + k0, WS_H);
                wmma::load_matrix_sync(bL, WSh + WSL + (nt * 16) * WS_H + k0, WS_H);
                wmma::mma_sync(acc[j], aH, bH, acc[j]);
                wmma::mma_sync(acc[j], aH, bL, acc[j]);
                wmma::mma_sync(acc[j], aL, bH, acc[j]);
            }
        }
        __syncthreads();
    }

#pragma unroll
    for (int j = 0; j < 4; j++) {
        const int nt = nh * 4 + j;
        wmma::store_matrix_sync(Df + (mt * 16) * F0S + nt * 16, acc[j], F0S,
                                wmma::mem_row_major);
    }
}

__global__ void __launch_bounds__(TPB, 1)
evsr_kernel(const float* __restrict__ tf, const float* __restrict__ sf,
            const float* __restrict__ lnw, const float* __restrict__ lnb,
            float* __restrict__ out)
{
    extern __shared__ char smem[];
    bf16*  XQh = (bf16*)(smem + OFF_XQ);
    bf16*  XSh = (bf16*)(smem + OFF_XS);
    bf16*  KAh = (bf16*)(smem + OFF_KA);
    bf16*  Pb  = (bf16*)(smem + OFF_P);
    float* F0  = (float*)(smem + OFF_F0);
    float* F1  = (float*)(smem + OFF_F1);
    float* LNF = (float*)(smem + OFF_LN);

    const int tid = threadIdx.x;
    const int w   = tid >> 5;
    const int blk = blockIdx.x;
    const int b   = blk >> 10;
    const int wy  = (blk >> 5) & 31;
    const int wx  = blk & 31;
    const int base = ((b * CH) << 16) + ((wy * WSZ) << 8) + (wx * WSZ);

    // ---- Phase 1: load windows, split hi/lo ----
#pragma unroll
    for (int k = 0; k < 32; k++) {
        int idx = tid + k * TPB;
        int c = idx >> 6, t = idx & 63;
        int g = base + (c << 16) + ((t >> 3) << 8) + (t & 7);
        bf16 h, l;
        split_bf(tf[g], h, l);
        XQh[t * XS_H + c] = h; XQh[HL + t * XS_H + c] = l;
        split_bf(sf[g], h, l);
        XSh[t * XS_H + c] = h; XSh[HL + t * XS_H + c] = l;
    }
    LNF[tid] = (tid < 128) ? lnw[tid] : lnb[tid - 128];
    __syncthreads();

    // ---- Phase 2: Q projection, RoPE, K projection, RoPE, V projection ----
    proj_wmma(smem, XQh, 0, F0, tid);      // Qf -> F0
    __syncthreads();
    // RoPE Q: F0 -> XQ region (hi/lo)
#pragma unroll
    for (int k = 0; k < 16; k++) {
        int idx = tid + k * TPB;           // 4096 = t(64) h(4) i(16)
        int i = idx & 15, h = (idx >> 4) & 3, t = idx >> 6;
        float freq = exp2f(-(float)i * 0.830482023721841f);
        float ang = (float)((t >> 3) + (t & 7)) * freq;
        float sv, cv;
        __sincosf(ang, &sv, &cv);
        int c1 = h * 32 + i, c2 = c1 + 16;
        float q1 = F0[t * F0S + c1], q2 = F0[t * F0S + c2];
        bf16 hh, ll;
        split_bf(q1 * cv - q2 * sv, hh, ll);
        XQh[t * XS_H + c1] = hh; XQh[HL + t * XS_H + c1] = ll;
        split_bf(q1 * sv + q2 * cv, hh, ll);
        XQh[t * XS_H + c2] = hh; XQh[HL + t * XS_H + c2] = ll;
    }
    __syncthreads();

    proj_wmma(smem, XSh, 1, F0, tid);      // Kf -> F0
    __syncthreads();
    // RoPE K: F0 -> KA region
#pragma unroll
    for (int k = 0; k < 16; k++) {
        int idx = tid + k * TPB;
        int i = idx & 15, h = (idx >> 4) & 3, t = idx >> 6;
        float freq = exp2f(-(float)i * 0.830482023721841f);
        float ang = (float)((t >> 3) + (t & 7)) * freq;
        float sv, cv;
        __sincosf(ang, &sv, &cv);
        int c1 = h * 32 + i, c2 = c1 + 16;
        float k1 = F0[t * F0S + c1], k2 = F0[t * F0S + c2];
        bf16 hh, ll;
        split_bf(k1 * cv - k2 * sv, hh, ll);
        KAh[t * XS_H + c1] = hh; KAh[HL + t * XS_H + c1] = ll;
        split_bf(k1 * sv + k2 * cv, hh, ll);
        KAh[t * XS_H + c2] = hh; KAh[HL + t * XS_H + c2] = ll;
    }
    __syncthreads();

    proj_wmma(smem, XSh, 2, F0, tid);      // Vf -> F0
    __syncthreads();
    // V convert: F0 -> XS region
#pragma unroll
    for (int k = 0; k < 32; k++) {
        int idx = tid + k * TPB;
        int c = idx & 127, t = idx >> 7;
        bf16 h, l;
        split_bf(F0[t * F0S + c], h, l);
        XSh[t * XS_H + c] = h; XSh[HL + t * XS_H + c] = l;
    }
    __syncthreads();

    // ---- Phase 3: attention, two head-pairs ----
    const float scale = 0.17677669529663687f;
    const int hl = w >> 2;                 // head-local within pair
    const int mt = w & 3;

    for (int hp = 0; hp < 2; hp++) {
        const int head = hp * 2 + hl;

        // S = Q K^T : warp computes 16 rows x 64 cols for its head
        {
            FragC sacc[4];
#pragma unroll
            for (int j = 0; j < 4; j++) wmma::fill_fragment(sacc[j], 0.0f);
#pragma unroll
            for (int kt = 0; kt < 2; kt++) {
                FragA aH, aL;
                wmma::load_matrix_sync(aH, XQh + (mt * 16) * XS_H + head * 32 + kt * 16, XS_H);
                wmma::load_matrix_sync(aL, XQh + HL + (mt * 16) * XS_H + head * 32 + kt * 16, XS_H);
#pragma unroll
                for (int j = 0; j < 4; j++) {
                    FragBc bH, bL;
                    wmma::load_matrix_sync(bH, KAh + (j * 16) * XS_H + head * 32 + kt * 16, XS_H);
                    wmma::load_matrix_sync(bL, KAh + HL + (j * 16) * XS_H + head * 32 + kt * 16, XS_H);
                    wmma::mma_sync(sacc[j], aH, bH, sacc[j]);
                    wmma::mma_sync(sacc[j], aH, bL, sacc[j]);
                    wmma::mma_sync(sacc[j], aL, bH, sacc[j]);
                }
            }
#pragma unroll
            for (int j = 0; j < 4; j++)
                wmma::store_matrix_sync(F0 + hl * 4352 + (mt * 16) * SS + j * 16,
                                        sacc[j], SS, wmma::mem_row_major);
        }
        __syncthreads();

        // softmax: 2 threads per row over 128 rows (2 heads x 64)
        {
            int rid = tid >> 1, half = tid & 1;
            int shl = rid >> 6, row = rid & 63;
            float* Srow = F0 + shl * 4352 + row * SS + half * 32;
            float mx = -1e30f;
#pragma unroll 8
            for (int j = 0; j < 32; j++) mx = fmaxf(mx, Srow[j]);
            mx = fmaxf(mx, __shfl_xor_sync(0xffffffffu, mx, 1));
            float e[32], s = 0.0f;
#pragma unroll 8
            for (int j = 0; j < 32; j++) {
                e[j] = __expf((Srow[j] - mx) * scale);
                s += e[j];
            }
            s += __shfl_xor_sync(0xffffffffu, s, 1);
            float inv = 1.0f / s;
            bf16* Pdst = Pb + shl * 2 * PH + row * PS_H + half * 32;
#pragma unroll 8
            for (int j = 0; j < 32; j++) {
                bf16 h, l;
                split_bf(e[j] * inv, h, l);
                Pdst[j] = h; Pdst[PH + j] = l;
            }
        }
        __syncthreads();

        // O = P V : warp computes 16 rows x 32 cols for its head -> F1
        {
            const bf16* Pbase = Pb + hl * 2 * PH;
            FragC oacc[2];
            wmma::fill_fragment(oacc[0], 0.0f);
            wmma::fill_fragment(oacc[1], 0.0f);
#pragma unroll
            for (int kt = 0; kt < 4; kt++) {
                FragA aH, aL;
                wmma::load_matrix_sync(aH, Pbase + (mt * 16) * PS_H + kt * 16, PS_H);
                wmma::load_matrix_sync(aL, Pbase + PH + (mt * 16) * PS_H + kt * 16, PS_H);
#pragma unroll
                for (int j = 0; j < 2; j++) {
                    FragBr bH, bL;
                    wmma::load_matrix_sync(bH, XSh + (kt * 16) * XS_H + head * 32 + j * 16, XS_H);
                    wmma::load_matrix_sync(bL, XSh + HL + (kt * 16) * XS_H + head * 32 + j * 16, XS_H);
                    wmma::mma_sync(oacc[j], aH, bH, oacc[j]);
                    wmma::mma_sync(oacc[j], aH, bL, oacc[j]);
                    wmma::mma_sync(oacc[j], aL, bH, oacc[j]);
                }
            }
            wmma::store_matrix_sync(F1 + (mt * 16) * F1S + head * 32, oacc[0],
                                    F1S, wmma::mem_row_major);
            wmma::store_matrix_sync(F1 + (mt * 16) * F1S + head * 32 + 16, oacc[1],
                                    F1S, wmma::mem_row_major);
        }
        __syncthreads();
    }

    // ---- Phase 4: AO convert -> KA region; residual load -> F1 (after) ----
#pragma unroll
    for (int k = 0; k < 32; k++) {
        int idx = tid + k * TPB;
        int c = idx & 127, t = idx >> 7;
        bf16 h, l;
        split_bf(F1[t * F1S + c], h, l);
        KAh[t * XS_H + c] = h; KAh[HL + t * XS_H + c] = l;
    }
    __syncthreads();
#pragma unroll
    for (int k = 0; k < 32; k++) {
        int idx = tid + k * TPB;
        int c = idx >> 6, t = idx & 63;
        F1[t * F1S + c] = tf[base + (c << 16) + ((t >> 3) << 8) + (t & 7)];
    }

    // ---- Phase 5: output projection ----
    proj_wmma(smem, KAh, 3, F0, tid);
    __syncthreads();

    // ---- Phase 6: LayerNorm + residual, 4 threads per token ----
    {
        int t = tid >> 2, j = tid & 3;
        float* xr = F0 + t * F0S + j * 32;
        float s1 = 0.0f, s2 = 0.0f;
#pragma unroll 8
        for (int c = 0; c < 32; c++) {
            float v = xr[c];
            s1 += v;
            s2 += v * v;
        }
#pragma unroll
        for (int d = 1; d < 4; d <<= 1) {
            s1 += __shfl_xor_sync(0xffffffffu, s1, d, 4);
            s2 += __shfl_xor_sync(0xffffffffu, s2, d, 4);
        }
        float mu  = s1 * (1.0f / 128.0f);
        float var = s2 * (1.0f / 128.0f) - mu * mu;
        float inv = rsqrtf(var + 1e-5f);
        const float* resid = F1 + t * F1S + j * 32;
        const float* lw    = LNF + j * 32;
        const float* lb    = LNF + 128 + j * 32;
#pragma unroll 8
        for (int c = 0; c < 32; c++)
            xr[c] = (xr[c] - mu) * inv * lw[c] + lb[c] + resid[c];
    }
    __syncthreads();

    // ---- Phase 7: store ----
#pragma unroll
    for (int k = 0; k < 32; k++) {
        int idx = tid + k * TPB;
        int c = idx >> 6, t = idx & 63;
        out[base + (c << 16) + ((t >> 3) << 8) + (t & 7)] = F0[t * F0S + c];
    }
}

extern "C" void kernel_launch(void* const* d_in, const int* in_sizes, int n_in,
                              void* d_out, int out_size)
{
    const float* tf  = (const float*)d_in[0];
    const float* sf  = (const float*)d_in[1];
    const float* Wq  = (const float*)d_in[2];
    const float* Wk  = (const float*)d_in[3];
    const float* Wv  = (const float*)d_in[4];
    const float* Wo  = (const float*)d_in[5];
    const float* lnw = (const float*)d_in[6];
    const float* lnb = (const float*)d_in[7];
    float* out = (float*)d_out;

    int B = in_sizes[0] / (CH * IMG_H * IMG_W);
    if (B < 1) B = 1;
    int n_windows = B * (IMG_H / WSZ) * (IMG_W / WSZ);

    dim3 pg(64, 4);
    prep_kernel<<<pg, 256>>>(Wq, Wk, Wv, Wo);

    cudaFuncSetAttribute(evsr_kernel, cudaFuncAttributeMaxDynamicSharedMemorySize,
                         SMEM_BYTES);
    evsr_kernel<<<n_windows, TPB, SMEM_BYTES>>>(tf, sf, lnw, lnb, out);
}

// round 10
// speedup vs baseline: 1.7698x; 1.1686x over previous
#include <cuda_runtime.h>
#include <cuda_bf16.h>
#include <mma.h>
#include <math.h>

using namespace nvcuda;
typedef __nv_bfloat16 bf16;

// ---------------------------------------------------------------------------
// EfficientVSR windowed cross-attention, fused, WMMA bf16 (m16n16k16) with
// hi/lo 3-term compensation. One CTA (512 thr, 16 warps) per 8x8 window.
// Double-buffered weight staging (buf1 overlaps the attention P region).
// B=8, C=128, H=W=256, heads=4, hd=32.
// ---------------------------------------------------------------------------

constexpr int TPB   = 512;
constexpr int CH    = 128;
constexpr int IMG_H = 256;
constexpr int IMG_W = 256;
constexpr int WSZ   = 8;

constexpr int XS_H = 136;   // half stride for 64x128 bf16 tiles (mult of 8)
constexpr int WS_H = 40;    // weight slab half stride (32 + 8 pad)
constexpr int PS_H = 72;    // probs half stride
constexpr int F0S  = 132;   // F0 float stride for 128-wide
constexpr int SS   = 68;    // S strip float stride
constexpr int F1S  = 132;   // F1 float stride

// smem byte offsets
constexpr int OFF_XQ = 0;        // XQ hi/lo -> later Q hi/lo       34816
constexpr int OFF_XS = 34816;    // XS hi/lo -> later V hi/lo       34816
constexpr int OFF_KA = 69632;    // K hi/lo  -> later AO hi/lo      34816
constexpr int OFF_WS = 104448;   // weight slab buffer 0            20480
constexpr int OFF_P  = 124928;   // probs (attention) / weight buf1 36864
constexpr int OFF_F0 = 161792;   // fp32 scratch (proj out / S)     34816
constexpr int OFF_F1 = 196608;   // fp32 scratch (AO / residual)    33792
constexpr int OFF_LN = 230400;   // ln_w + ln_b                      1024
constexpr int SMEM_BYTES = 231424;

constexpr int HL  = 8704;  // half offset hi->lo within XQ/XS/KA (64*136)
constexpr int WSL = 5120;  // half offset hi->lo within a weight slab buffer
constexpr int PH  = 4608;  // halves per P half-buffer (64*72)

// prepped weights: plain [m][d][c] bf16 hi and lo
__device__ __align__(16) bf16 WHg[4 * 16384];
__device__ __align__(16) bf16 WLg[4 * 16384];

__device__ __forceinline__ void split_bf(float v, bf16& h, bf16& l) {
    h = __float2bfloat16_rn(v);
    l = __float2bfloat16_rn(v - __bfloat162float(h));
}

__global__ void __launch_bounds__(256) prep_kernel(
    const float* __restrict__ Wq, const float* __restrict__ Wk,
    const float* __restrict__ Wv, const float* __restrict__ Wo)
{
    int m = blockIdx.y;
    const float* Ws = (m == 0) ? Wq : (m == 1) ? Wk : (m == 2) ? Wv : Wo;
    int idx = blockIdx.x * 256 + threadIdx.x;   // 0..16383
    bf16 h, l;
    split_bf(Ws[idx], h, l);
    WHg[m * 16384 + idx] = h;
    WLg[m * 16384 + idx] = l;
}

typedef wmma::fragment<wmma::matrix_a, 16, 16, 16, bf16, wmma::row_major> FragA;
typedef wmma::fragment<wmma::matrix_b, 16, 16, 16, bf16, wmma::col_major> FragBc;
typedef wmma::fragment<wmma::matrix_b, 16, 16, 16, bf16, wmma::row_major> FragBr;
typedef wmma::fragment<wmma::accumulator, 16, 16, 16, float> FragC;

// D[64,128] = A[64,128] @ W_m^T. A = hi/lo bf16 at Ah (lo at +HL), stride XS_H.
// D fp32 at Df (stride F0S). Weights staged in 32-wide k slabs, double-buffered.
__device__ __forceinline__ void proj_wmma(char* smem, const bf16* Ah, int widx,
                                          float* Df, int tid)
{
    const int w  = tid >> 5;
    const int mt = w & 3;        // 16-row tile
    const int nh = w >> 2;       // 32-col group (2 n-tiles)

    bf16* buf0 = (bf16*)(smem + OFF_WS);
    bf16* buf1 = (bf16*)(smem + OFF_P);   // P region dead during projections

    FragC acc[2];
    wmma::fill_fragment(acc[0], 0.0f);
    wmma::fill_fragment(acc[1], 0.0f);

    const uint4* sH = (const uint4*)(WHg + widx * 16384);  // 16 uint4 per d-row
    const uint4* sL = (const uint4*)(WLg + widx * 16384);
    const int d  = tid >> 2;      // 0..127
    const int cp = tid & 3;       // uint4 within slab row

    // stage slab 0 into buf0
    {
        uint4* dH = (uint4*)buf0;           // 5 uint4 per d-row (40 halves)
        uint4* dL = (uint4*)(buf0 + WSL);
        dH[d * 5 + cp] = sH[d * 16 + cp];
        dL[d * 5 + cp] = sL[d * 16 + cp];
    }
    __syncthreads();

#pragma unroll
    for (int s = 0; s < 4; s++) {
        bf16* B  = (s & 1) ? buf1 : buf0;
        bf16* Bn = (s & 1) ? buf0 : buf1;

        uint4 pH, pL;
        if (s < 3) {            // prefetch next slab (global -> regs)
            pH = sH[d * 16 + (s + 1) * 4 + cp];
            pL = sL[d * 16 + (s + 1) * 4 + cp];
        }

#pragma unroll
        for (int ktl = 0; ktl < 2; ktl++) {
            const int k0 = ktl * 16;
            FragA aH, aL;
            wmma::load_matrix_sync(aH, Ah + (mt * 16) * XS_H + s * 32 + k0, XS_H);
            wmma::load_matrix_sync(aL, Ah + HL + (mt * 16) * XS_H + s * 32 + k0, XS_H);
#pragma unroll
            for (int j = 0; j < 2; j++) {
                const int nt = nh * 2 + j;
                FragBc bH, bL;
                wmma::load_matrix_sync(bH, B + (nt * 16) * WS_H + k0, WS_H);
                wmma::load_matrix_sync(bL, B + WSL + (nt * 16) * WS_H + k0, WS_H);
                wmma::mma_sync(acc[j], aH, bH, acc[j]);
                wmma::mma_sync(acc[j], aH, bL, acc[j]);
                wmma::mma_sync(acc[j], aL, bH, acc[j]);
            }
        }

        if (s < 3) {            // store prefetched slab into alternate buffer
            uint4* dH = (uint4*)Bn;
            uint4* dL = (uint4*)(Bn + WSL);
            dH[d * 5 + cp] = pH;
            dL[d * 5 + cp] = pL;
        }
        __syncthreads();
    }

#pragma unroll
    for (int j = 0; j < 2; j++)
        wmma::store_matrix_sync(Df + (mt * 16) * F0S + nh * 32 + j * 16, acc[j],
                                F0S, wmma::mem_row_major);
}

__global__ void __launch_bounds__(TPB, 1)
evsr_kernel(const float* __restrict__ tf, const float* __restrict__ sf,
            const float* __restrict__ lnw, const float* __restrict__ lnb,
            float* __restrict__ out)
{
    extern __shared__ char smem[];
    bf16*  XQh = (bf16*)(smem + OFF_XQ);
    bf16*  XSh = (bf16*)(smem + OFF_XS);
    bf16*  KAh = (bf16*)(smem + OFF_KA);
    bf16*  Pb  = (bf16*)(smem + OFF_P);
    float* F0  = (float*)(smem + OFF_F0);
    float* F1  = (float*)(smem + OFF_F1);
    float* LNF = (float*)(smem + OFF_LN);

    const int tid = threadIdx.x;
    const int w   = tid >> 5;
    const int blk = blockIdx.x;
    const int b   = blk >> 10;
    const int wy  = (blk >> 5) & 31;
    const int wx  = blk & 31;
    const int base = ((b * CH) << 16) + ((wy * WSZ) << 8) + (wx * WSZ);

    // ---- Phase 1: load windows, split hi/lo ----
#pragma unroll
    for (int k = 0; k < 16; k++) {
        int idx = tid + k * TPB;
        int c = idx >> 6, t = idx & 63;
        int g = base + (c << 16) + ((t >> 3) << 8) + (t & 7);
        bf16 h, l;
        split_bf(tf[g], h, l);
        XQh[t * XS_H + c] = h; XQh[HL + t * XS_H + c] = l;
        split_bf(sf[g], h, l);
        XSh[t * XS_H + c] = h; XSh[HL + t * XS_H + c] = l;
    }
    if (tid < 256) LNF[tid] = (tid < 128) ? lnw[tid] : lnb[tid - 128];
    __syncthreads();

    // ---- Phase 2: Q proj, RoPE Q, K proj, RoPE K, V proj, V convert ----
    proj_wmma(smem, XQh, 0, F0, tid);      // Qf -> F0
    __syncthreads();
#pragma unroll
    for (int k = 0; k < 8; k++) {          // RoPE Q: F0 -> XQ hi/lo
        int idx = tid + k * TPB;           // 4096 = t(64) h(4) i(16)
        int i = idx & 15, h = (idx >> 4) & 3, t = idx >> 6;
        float freq = exp2f(-(float)i * 0.830482023721841f);
        float ang = (float)((t >> 3) + (t & 7)) * freq;
        float sv, cv;
        __sincosf(ang, &sv, &cv);
        int c1 = h * 32 + i, c2 = c1 + 16;
        float q1 = F0[t * F0S + c1], q2 = F0[t * F0S + c2];
        bf16 hh, ll;
        split_bf(q1 * cv - q2 * sv, hh, ll);
        XQh[t * XS_H + c1] = hh; XQh[HL + t * XS_H + c1] = ll;
        split_bf(q1 * sv + q2 * cv, hh, ll);
        XQh[t * XS_H + c2] = hh; XQh[HL + t * XS_H + c2] = ll;
    }
    __syncthreads();

    proj_wmma(smem, XSh, 1, F0, tid);      // Kf -> F0
    __syncthreads();
#pragma unroll
    for (int k = 0; k < 8; k++) {          // RoPE K: F0 -> KA hi/lo
        int idx = tid + k * TPB;
        int i = idx & 15, h = (idx >> 4) & 3, t = idx >> 6;
        float freq = exp2f(-(float)i * 0.830482023721841f);
        float ang = (float)((t >> 3) + (t & 7)) * freq;
        float sv, cv;
        __sincosf(ang, &sv, &cv);
        int c1 = h * 32 + i, c2 = c1 + 16;
        float k1 = F0[t * F0S + c1], k2 = F0[t * F0S + c2];
        bf16 hh, ll;
        split_bf(k1 * cv - k2 * sv, hh, ll);
        KAh[t * XS_H + c1] = hh; KAh[HL + t * XS_H + c1] = ll;
        split_bf(k1 * sv + k2 * cv, hh, ll);
        KAh[t * XS_H + c2] = hh; KAh[HL + t * XS_H + c2] = ll;
    }
    __syncthreads();

    proj_wmma(smem, XSh, 2, F0, tid);      // Vf -> F0
    __syncthreads();
#pragma unroll
    for (int k = 0; k < 16; k++) {         // V convert: F0 -> XS hi/lo
        int idx = tid + k * TPB;
        int c = idx & 127, t = idx >> 7;
        bf16 h, l;
        split_bf(F0[t * F0S + c], h, l);
        XSh[t * XS_H + c] = h; XSh[HL + t * XS_H + c] = l;
    }
    __syncthreads();

    // ---- Phase 3: attention, two head-pair passes, 16 warps each ----
    const float scale = 0.17677669529663687f;
    const int hl  = w >> 3;                // head-local within pair
    const int amt = (w >> 1) & 3;          // 16-row tile
    const int anf = w & 1;                 // 32-col half (S) / 16-col tile (PV)

    for (int hp = 0; hp < 2; hp++) {
        const int head = hp * 2 + hl;

        // S = Q K^T : warp computes 16 rows x 32 cols of its head
        {
            FragC sacc[2];
            wmma::fill_fragment(sacc[0], 0.0f);
            wmma::fill_fragment(sacc[1], 0.0f);
#pragma unroll
            for (int kt = 0; kt < 2; kt++) {
                FragA aH, aL;
                wmma::load_matrix_sync(aH, XQh + (amt * 16) * XS_H + head * 32 + kt * 16, XS_H);
                wmma::load_matrix_sync(aL, XQh + HL + (amt * 16) * XS_H + head * 32 + kt * 16, XS_H);
#pragma unroll
                for (int j = 0; j < 2; j++) {
                    const int n0 = anf * 32 + j * 16;
                    FragBc bH, bL;
                    wmma::load_matrix_sync(bH, KAh + n0 * XS_H + head * 32 + kt * 16, XS_H);
                    wmma::load_matrix_sync(bL, KAh + HL + n0 * XS_H + head * 32 + kt * 16, XS_H);
                    wmma::mma_sync(sacc[j], aH, bH, sacc[j]);
                    wmma::mma_sync(sacc[j], aH, bL, sacc[j]);
                    wmma::mma_sync(sacc[j], aL, bH, sacc[j]);
                }
            }
#pragma unroll
            for (int j = 0; j < 2; j++)
                wmma::store_matrix_sync(F0 + hl * 4352 + (amt * 16) * SS + anf * 32 + j * 16,
                                        sacc[j], SS, wmma::mem_row_major);
        }
        __syncthreads();

        // softmax: 4 threads per row, 128 rows (2 heads x 64)
        {
            int rid = tid >> 2, q = tid & 3;
            int shl = rid >> 6, row = rid & 63;
            float* Srow = F0 + shl * 4352 + row * SS + q * 16;
            float mx = -1e30f;
#pragma unroll
            for (int j = 0; j < 16; j++) mx = fmaxf(mx, Srow[j]);
            mx = fmaxf(mx, __shfl_xor_sync(0xffffffffu, mx, 1, 4));
            mx = fmaxf(mx, __shfl_xor_sync(0xffffffffu, mx, 2, 4));
            float e[16], s = 0.0f;
#pragma unroll
            for (int j = 0; j < 16; j++) {
                e[j] = __expf((Srow[j] - mx) * scale);
                s += e[j];
            }
            s += __shfl_xor_sync(0xffffffffu, s, 1, 4);
            s += __shfl_xor_sync(0xffffffffu, s, 2, 4);
            float inv = 1.0f / s;
            bf16* Pdst = Pb + shl * 2 * PH + row * PS_H + q * 16;
#pragma unroll
            for (int j = 0; j < 16; j++) {
                bf16 h, l;
                split_bf(e[j] * inv, h, l);
                Pdst[j] = h; Pdst[PH + j] = l;
            }
        }
        __syncthreads();

        // O = P V : warp computes one 16x16 tile of its head -> F1
        {
            const bf16* Pbase = Pb + hl * 2 * PH;
            FragC oacc;
            wmma::fill_fragment(oacc, 0.0f);
#pragma unroll
            for (int kt = 0; kt < 4; kt++) {
                FragA aH, aL;
                wmma::load_matrix_sync(aH, Pbase + (amt * 16) * PS_H + kt * 16, PS_H);
                wmma::load_matrix_sync(aL, Pbase + PH + (amt * 16) * PS_H + kt * 16, PS_H);
                FragBr bH, bL;
                wmma::load_matrix_sync(bH, XSh + (kt * 16) * XS_H + head * 32 + anf * 16, XS_H);
                wmma::load_matrix_sync(bL, XSh + HL + (kt * 16) * XS_H + head * 32 + anf * 16, XS_H);
                wmma::mma_sync(oacc, aH, bH, oacc);
                wmma::mma_sync(oacc, aH, bL, oacc);
                wmma::mma_sync(oacc, aL, bH, oacc);
            }
            wmma::store_matrix_sync(F1 + (amt * 16) * F1S + head * 32 + anf * 16,
                                    oacc, F1S, wmma::mem_row_major);
        }
        __syncthreads();
    }

    // ---- Phase 4: AO convert -> KA region; then residual reload -> F1 ----
#pragma unroll
    for (int k = 0; k < 16; k++) {
        int idx = tid + k * TPB;
        int c = idx & 127, t = idx >> 7;
        bf16 h, l;
        split_bf(F1[t * F1S + c], h, l);
        KAh[t * XS_H + c] = h; KAh[HL + t * XS_H + c] = l;
    }
    __syncthreads();
#pragma unroll
    for (int k = 0; k < 16; k++) {
        int idx = tid + k * TPB;
        int c = idx >> 6, t = idx & 63;
        F1[t * F1S + c] = tf[base + (c << 16) + ((t >> 3) << 8) + (t & 7)];
    }

    // ---- Phase 5: output projection (KA @ Wo^T -> F0) ----
    proj_wmma(smem, KAh, 3, F0, tid);
    __syncthreads();

    // ---- Phase 6: LayerNorm + residual, 8 threads per token ----
    {
        int t = tid >> 3, j = tid & 7;
        float* xr = F0 + t * F0S + j * 16;
        float s1 = 0.0f, s2 = 0.0f;
#pragma unroll
        for (int g = 0; g < 4; g++) {
            float4 v = *(const float4*)(xr + g * 4);
            s1 += v.x + v.y + v.z + v.w;
            s2 += v.x * v.x + v.y * v.y + v.z * v.z + v.w * v.w;
        }
#pragma unroll
        for (int d = 1; d < 8; d <<= 1) {
            s1 += __shfl_xor_sync(0xffffffffu, s1, d, 8);
            s2 += __shfl_xor_sync(0xffffffffu, s2, d, 8);
        }
        float mu  = s1 * (1.0f / 128.0f);
        float var = s2 * (1.0f / 128.0f) - mu * mu;
        float inv = rsqrtf(var + 1e-5f);
        const float* resid = F1 + t * F1S + j * 16;
        const float* lw    = LNF + j * 16;
        const float* lb    = LNF + 128 + j * 16;
#pragma unroll
        for (int c = 0; c < 16; c++)
            xr[c] = (xr[c] - mu) * inv * lw[c] + lb[c] + resid[c];
    }
    __syncthreads();

    // ---- Phase 7: store ----
#pragma unroll
    for (int k = 0; k < 16; k++) {
        int idx = tid + k * TPB;
        int c = idx >> 6, t = idx & 63;
        out[base + (c << 16) + ((t >> 3) << 8) + (t & 7)] = F0[t * F0S + c];
    }
}

extern "C" void kernel_launch(void* const* d_in, const int* in_sizes, int n_in,
                              void* d_out, int out_size)
{
    const float* tf  = (const float*)d_in[0];
    const float* sf  = (const float*)d_in[1];
    const float* Wq  = (const float*)d_in[2];
    const float* Wk  = (const float*)d_in[3];
    const float* Wv  = (const float*)d_in[4];
    const float* Wo  = (const float*)d_in[5];
    const float* lnw = (const float*)d_in[6];
    const float* lnb = (const float*)d_in[7];
    float* out = (float*)d_out;

    int B = in_sizes[0] / (CH * IMG_H * IMG_W);
    if (B < 1) B = 1;
    int n_windows = B * (IMG_H / WSZ) * (IMG_W / WSZ);

    dim3 pg(64, 4);
    prep_kernel<<<pg, 256>>>(Wq, Wk, Wv, Wo);

    cudaFuncSetAttribute(evsr_kernel, cudaFuncAttributeMaxDynamicSharedMemorySize,
                         SMEM_BYTES);
    evsr_kernel<<<n_windows, TPB, SMEM_BYTES>>>(tf, sf, lnw, lnb, out);
}

// round 11
// speedup vs baseline: 1.7700x; 1.0002x over previous
#include <cuda_runtime.h>
#include <cuda_bf16.h>
#include <mma.h>
#include <math.h>

using namespace nvcuda;
typedef __nv_bfloat16 bf16;

// ---------------------------------------------------------------------------
// EfficientVSR windowed cross-attention, fused, WMMA bf16 (m16n16k16) with
// hi/lo 3-term compensation. One CTA (512 thr, 16 warps) per 8x8 window.
// Double-buffered weight staging (buf1 overlaps the attention P region).
// B=8, C=128, H=W=256, heads=4, hd=32.
// ---------------------------------------------------------------------------

constexpr int TPB   = 512;
constexpr int CH    = 128;
constexpr int IMG_H = 256;
constexpr int IMG_W = 256;
constexpr int WSZ   = 8;

constexpr int XS_H = 136;   // half stride for 64x128 bf16 tiles (mult of 8)
constexpr int WS_H = 40;    // weight slab half stride (32 + 8 pad)
constexpr int PS_H = 72;    // probs half stride
constexpr int F0S  = 132;   // F0 float stride for 128-wide
constexpr int SS   = 68;    // S strip float stride
constexpr int F1S  = 132;   // F1 float stride

// smem byte offsets
constexpr int OFF_XQ = 0;        // XQ hi/lo -> later Q hi/lo       34816
constexpr int OFF_XS = 34816;    // XS hi/lo -> later V hi/lo       34816
constexpr int OFF_KA = 69632;    // K hi/lo  -> later AO hi/lo      34816
constexpr int OFF_WS = 104448;   // weight slab buffer 0            20480
constexpr int OFF_P  = 124928;   // probs (attention) / weight buf1 36864
constexpr int OFF_F0 = 161792;   // fp32 scratch (proj out / S)     34816
constexpr int OFF_F1 = 196608;   // fp32 scratch (AO / residual)    33792
constexpr int OFF_LN = 230400;   // ln_w + ln_b                      1024
constexpr int SMEM_BYTES = 231424;

constexpr int HL  = 8704;  // half offset hi->lo within XQ/XS/KA (64*136)
constexpr int WSL = 5120;  // half offset hi->lo within a weight slab buffer
constexpr int PH  = 4608;  // halves per P half-buffer (64*72)

// prepped weights: plain [m][d][c] bf16 hi and lo
__device__ __align__(16) bf16 WHg[4 * 16384];
__device__ __align__(16) bf16 WLg[4 * 16384];

__device__ __forceinline__ void split_bf(float v, bf16& h, bf16& l) {
    h = __float2bfloat16_rn(v);
    l = __float2bfloat16_rn(v - __bfloat162float(h));
}

__global__ void __launch_bounds__(256) prep_kernel(
    const float* __restrict__ Wq, const float* __restrict__ Wk,
    const float* __restrict__ Wv, const float* __restrict__ Wo)
{
    int m = blockIdx.y;
    const float* Ws = (m == 0) ? Wq : (m == 1) ? Wk : (m == 2) ? Wv : Wo;
    int idx = blockIdx.x * 256 + threadIdx.x;   // 0..16383
    bf16 h, l;
    split_bf(Ws[idx], h, l);
    WHg[m * 16384 + idx] = h;
    WLg[m * 16384 + idx] = l;
}

typedef wmma::fragment<wmma::matrix_a, 16, 16, 16, bf16, wmma::row_major> FragA;
typedef wmma::fragment<wmma::matrix_b, 16, 16, 16, bf16, wmma::col_major> FragBc;
typedef wmma::fragment<wmma::matrix_b, 16, 16, 16, bf16, wmma::row_major> FragBr;
typedef wmma::fragment<wmma::accumulator, 16, 16, 16, float> FragC;

// D[64,128] = A[64,128] @ W_m^T. A = hi/lo bf16 at Ah (lo at +HL), stride XS_H.
// D fp32 at Df (stride F0S). Weights staged in 32-wide k slabs, double-buffered.
__device__ __forceinline__ void proj_wmma(char* smem, const bf16* Ah, int widx,
                                          float* Df, int tid)
{
    const int w  = tid >> 5;
    const int mt = w & 3;        // 16-row tile
    const int nh = w >> 2;       // 32-col group (2 n-tiles)

    bf16* buf0 = (bf16*)(smem + OFF_WS);
    bf16* buf1 = (bf16*)(smem + OFF_P);   // P region dead during projections

    FragC acc[2];
    wmma::fill_fragment(acc[0], 0.0f);
    wmma::fill_fragment(acc[1], 0.0f);

    const uint4* sH = (const uint4*)(WHg + widx * 16384);  // 16 uint4 per d-row
    const uint4* sL = (const uint4*)(WLg + widx * 16384);
    const int d  = tid >> 2;      // 0..127
    const int cp = tid & 3;       // uint4 within slab row

    // stage slab 0 into buf0
    {
        uint4* dH = (uint4*)buf0;           // 5 uint4 per d-row (40 halves)
        uint4* dL = (uint4*)(buf0 + WSL);
        dH[d * 5 + cp] = sH[d * 16 + cp];
        dL[d * 5 + cp] = sL[d * 16 + cp];
    }
    __syncthreads();

#pragma unroll
    for (int s = 0; s < 4; s++) {
        bf16* B  = (s & 1) ? buf1 : buf0;
        bf16* Bn = (s & 1) ? buf0 : buf1;

        uint4 pH, pL;
        if (s < 3) {            // prefetch next slab (global -> regs)
            pH = sH[d * 16 + (s + 1) * 4 + cp];
            pL = sL[d * 16 + (s + 1) * 4 + cp];
        }

#pragma unroll
        for (int ktl = 0; ktl < 2; ktl++) {
            const int k0 = ktl * 16;
            FragA aH, aL;
            wmma::load_matrix_sync(aH, Ah + (mt * 16) * XS_H + s * 32 + k0, XS_H);
            wmma::load_matrix_sync(aL, Ah + HL + (mt * 16) * XS_H + s * 32 + k0, XS_H);
#pragma unroll
            for (int j = 0; j < 2; j++) {
                const int nt = nh * 2 + j;
                FragBc bH, bL;
                wmma::load_matrix_sync(bH, B + (nt * 16) * WS_H + k0, WS_H);
                wmma::load_matrix_sync(bL, B + WSL + (nt * 16) * WS_H + k0, WS_H);
                wmma::mma_sync(acc[j], aH, bH, acc[j]);
                wmma::mma_sync(acc[j], aH, bL, acc[j]);
                wmma::mma_sync(acc[j], aL, bH, acc[j]);
            }
        }

        if (s < 3) {            // store prefetched slab into alternate buffer
            uint4* dH = (uint4*)Bn;
            uint4* dL = (uint4*)(Bn + WSL);
            dH[d * 5 + cp] = pH;
            dL[d * 5 + cp] = pL;
        }
        __syncthreads();
    }

#pragma unroll
    for (int j = 0; j < 2; j++)
        wmma::store_matrix_sync(Df + (mt * 16) * F0S + nh * 32 + j * 16, acc[j],
                                F0S, wmma::mem_row_major);
}

__global__ void __launch_bounds__(TPB, 1)
evsr_kernel(const float* __restrict__ tf, const float* __restrict__ sf,
            const float* __restrict__ lnw, const float* __restrict__ lnb,
            float* __restrict__ out)
{
    extern __shared__ char smem[];
    bf16*  XQh = (bf16*)(smem + OFF_XQ);
    bf16*  XSh = (bf16*)(smem + OFF_XS);
    bf16*  KAh = (bf16*)(smem + OFF_KA);
    bf16*  Pb  = (bf16*)(smem + OFF_P);
    float* F0  = (float*)(smem + OFF_F0);
    float* F1  = (float*)(smem + OFF_F1);
    float* LNF = (float*)(smem + OFF_LN);

    const int tid = threadIdx.x;
    const int w   = tid >> 5;
    const int blk = blockIdx.x;
    const int b   = blk >> 10;
    const int wy  = (blk >> 5) & 31;
    const int wx  = blk & 31;
    const int base = ((b * CH) << 16) + ((wy * WSZ) << 8) + (wx * WSZ);

    // ---- Phase 1: load windows, split hi/lo ----
#pragma unroll
    for (int k = 0; k < 16; k++) {
        int idx = tid + k * TPB;
        int c = idx >> 6, t = idx & 63;
        int g = base + (c << 16) + ((t >> 3) << 8) + (t & 7);
        bf16 h, l;
        split_bf(tf[g], h, l);
        XQh[t * XS_H + c] = h; XQh[HL + t * XS_H + c] = l;
        split_bf(sf[g], h, l);
        XSh[t * XS_H + c] = h; XSh[HL + t * XS_H + c] = l;
    }
    if (tid < 256) LNF[tid] = (tid < 128) ? lnw[tid] : lnb[tid - 128];
    __syncthreads();

    // ---- Phase 2: Q proj, RoPE Q, K proj, RoPE K, V proj, V convert ----
    proj_wmma(smem, XQh, 0, F0, tid);      // Qf -> F0
    __syncthreads();
#pragma unroll
    for (int k = 0; k < 8; k++) {          // RoPE Q: F0 -> XQ hi/lo
        int idx = tid + k * TPB;           // 4096 = t(64) h(4) i(16)
        int i = idx & 15, h = (idx >> 4) & 3, t = idx >> 6;
        float freq = exp2f(-(float)i * 0.830482023721841f);
        float ang = (float)((t >> 3) + (t & 7)) * freq;
        float sv, cv;
        __sincosf(ang, &sv, &cv);
        int c1 = h * 32 + i, c2 = c1 + 16;
        float q1 = F0[t * F0S + c1], q2 = F0[t * F0S + c2];
        bf16 hh, ll;
        split_bf(q1 * cv - q2 * sv, hh, ll);
        XQh[t * XS_H + c1] = hh; XQh[HL + t * XS_H + c1] = ll;
        split_bf(q1 * sv + q2 * cv, hh, ll);
        XQh[t * XS_H + c2] = hh; XQh[HL + t * XS_H + c2] = ll;
    }
    __syncthreads();

    proj_wmma(smem, XSh, 1, F0, tid);      // Kf -> F0
    __syncthreads();
#pragma unroll
    for (int k = 0; k < 8; k++) {          // RoPE K: F0 -> KA hi/lo
        int idx = tid + k * TPB;
        int i = idx & 15, h = (idx >> 4) & 3, t = idx >> 6;
        float freq = exp2f(-(float)i * 0.830482023721841f);
        float ang = (float)((t >> 3) + (t & 7)) * freq;
        float sv, cv;
        __sincosf(ang, &sv, &cv);
        int c1 = h * 32 + i, c2 = c1 + 16;
        float k1 = F0[t * F0S + c1], k2 = F0[t * F0S + c2];
        bf16 hh, ll;
        split_bf(k1 * cv - k2 * sv, hh, ll);
        KAh[t * XS_H + c1] = hh; KAh[HL + t * XS_H + c1] = ll;
        split_bf(k1 * sv + k2 * cv, hh, ll);
        KAh[t * XS_H + c2] = hh; KAh[HL + t * XS_H + c2] = ll;
    }
    __syncthreads();

    proj_wmma(smem, XSh, 2, F0, tid);      // Vf -> F0
    __syncthreads();
#pragma unroll
    for (int k = 0; k < 16; k++) {         // V convert: F0 -> XS hi/lo
        int idx = tid + k * TPB;
        int c = idx & 127, t = idx >> 7;
        bf16 h, l;
        split_bf(F0[t * F0S + c], h, l);
        XSh[t * XS_H + c] = h; XSh[HL + t * XS_H + c] = l;
    }
    __syncthreads();

    // ---- Phase 3: attention, two head-pair passes, 16 warps each ----
    const float scale = 0.17677669529663687f;
    const int hl  = w >> 3;                // head-local within pair
    const int amt = (w >> 1) & 3;          // 16-row tile
    const int anf = w & 1;                 // 32-col half (S) / 16-col tile (PV)

    for (int hp = 0; hp < 2; hp++) {
        const int head = hp * 2 + hl;

        // S = Q K^T : warp computes 16 rows x 32 cols of its head
        {
            FragC sacc[2];
            wmma::fill_fragment(sacc[0], 0.0f);
            wmma::fill_fragment(sacc[1], 0.0f);
#pragma unroll
            for (int kt = 0; kt < 2; kt++) {
                FragA aH, aL;
                wmma::load_matrix_sync(aH, XQh + (amt * 16) * XS_H + head * 32 + kt * 16, XS_H);
                wmma::load_matrix_sync(aL, XQh + HL + (amt * 16) * XS_H + head * 32 + kt * 16, XS_H);
#pragma unroll
                for (int j = 0; j < 2; j++) {
                    const int n0 = anf * 32 + j * 16;
                    FragBc bH, bL;
                    wmma::load_matrix_sync(bH, KAh + n0 * XS_H + head * 32 + kt * 16, XS_H);
                    wmma::load_matrix_sync(bL, KAh + HL + n0 * XS_H + head * 32 + kt * 16, XS_H);
                    wmma::mma_sync(sacc[j], aH, bH, sacc[j]);
                    wmma::mma_sync(sacc[j], aH, bL, sacc[j]);
                    wmma::mma_sync(sacc[j], aL, bH, sacc[j]);
                }
            }
#pragma unroll
            for (int j = 0; j < 2; j++)
                wmma::store_matrix_sync(F0 + hl * 4352 + (amt * 16) * SS + anf * 32 + j * 16,
                                        sacc[j], SS, wmma::mem_row_major);
        }
        __syncthreads();

        // softmax: 4 threads per row, 128 rows (2 heads x 64)
        {
            int rid = tid >> 2, q = tid & 3;
            int shl = rid >> 6, row = rid & 63;
            float* Srow = F0 + shl * 4352 + row * SS + q * 16;
            float mx = -1e30f;
#pragma unroll
            for (int j = 0; j < 16; j++) mx = fmaxf(mx, Srow[j]);
            mx = fmaxf(mx, __shfl_xor_sync(0xffffffffu, mx, 1, 4));
            mx = fmaxf(mx, __shfl_xor_sync(0xffffffffu, mx, 2, 4));
            float e[16], s = 0.0f;
#pragma unroll
            for (int j = 0; j < 16; j++) {
                e[j] = __expf((Srow[j] - mx) * scale);
                s += e[j];
            }
            s += __shfl_xor_sync(0xffffffffu, s, 1, 4);
            s += __shfl_xor_sync(0xffffffffu, s, 2, 4);
            float inv = 1.0f / s;
            bf16* Pdst = Pb + shl * 2 * PH + row * PS_H + q * 16;
#pragma unroll
            for (int j = 0; j < 16; j++) {
                bf16 h, l;
                split_bf(e[j] * inv, h, l);
                Pdst[j] = h; Pdst[PH + j] = l;
            }
        }
        __syncthreads();

        // O = P V : warp computes one 16x16 tile of its head -> F1
        {
            const bf16* Pbase = Pb + hl * 2 * PH;
            FragC oacc;
            wmma::fill_fragment(oacc, 0.0f);
#pragma unroll
            for (int kt = 0; kt < 4; kt++) {
                FragA aH, aL;
                wmma::load_matrix_sync(aH, Pbase + (amt * 16) * PS_H + kt * 16, PS_H);
                wmma::load_matrix_sync(aL, Pbase + PH + (amt * 16) * PS_H + kt * 16, PS_H);
                FragBr bH, bL;
                wmma::load_matrix_sync(bH, XSh + (kt * 16) * XS_H + head * 32 + anf * 16, XS_H);
                wmma::load_matrix_sync(bL, XSh + HL + (kt * 16) * XS_H + head * 32 + anf * 16, XS_H);
                wmma::mma_sync(oacc, aH, bH, oacc);
                wmma::mma_sync(oacc, aH, bL, oacc);
                wmma::mma_sync(oacc, aL, bH, oacc);
            }
            wmma::store_matrix_sync(F1 + (amt * 16) * F1S + head * 32 + anf * 16,
                                    oacc, F1S, wmma::mem_row_major);
        }
        __syncthreads();
    }

    // ---- Phase 4: AO convert -> KA region; then residual reload -> F1 ----
#pragma unroll
    for (int k = 0; k < 16; k++) {
        int idx = tid + k * TPB;
        int c = idx & 127, t = idx >> 7;
        bf16 h, l;
        split_bf(F1[t * F1S + c], h, l);
        KAh[t * XS_H + c] = h; KAh[HL + t * XS_H + c] = l;
    }
    __syncthreads();
#pragma unroll
    for (int k = 0; k < 16; k++) {
        int idx = tid + k * TPB;
        int c = idx >> 6, t = idx & 63;
        F1[t * F1S + c] = tf[base + (c << 16) + ((t >> 3) << 8) + (t & 7)];
    }

    // ---- Phase 5: output projection (KA @ Wo^T -> F0) ----
    proj_wmma(smem, KAh, 3, F0, tid);
    __syncthreads();

    // ---- Phase 6: LayerNorm + residual, 8 threads per token ----
    {
        int t = tid >> 3, j = tid & 7;
        float* xr = F0 + t * F0S + j * 16;
        float s1 = 0.0f, s2 = 0.0f;
#pragma unroll
        for (int g = 0; g < 4; g++) {
            float4 v = *(const float4*)(xr + g * 4);
            s1 += v.x + v.y + v.z + v.w;
            s2 += v.x * v.x + v.y * v.y + v.z * v.z + v.w * v.w;
        }
#pragma unroll
        for (int d = 1; d < 8; d <<= 1) {
            s1 += __shfl_xor_sync(0xffffffffu, s1, d, 8);
            s2 += __shfl_xor_sync(0xffffffffu, s2, d, 8);
        }
        float mu  = s1 * (1.0f / 128.0f);
        float var = s2 * (1.0f / 128.0f) - mu * mu;
        float inv = rsqrtf(var + 1e-5f);
        const float* resid = F1 + t * F1S + j * 16;
        const float* lw    = LNF + j * 16;
        const float* lb    = LNF + 128 + j * 16;
#pragma unroll
        for (int c = 0; c < 16; c++)
            xr[c] = (xr[c] - mu) * inv * lw[c] + lb[c] + resid[c];
    }
    __syncthreads();

    // ---- Phase 7: store ----
#pragma unroll
    for (int k = 0; k < 16; k++) {
        int idx = tid + k * TPB;
        int c = idx >> 6, t = idx & 63;
        out[base + (c << 16) + ((t >> 3) << 8) + (t & 7)] = F0[t * F0S + c];
    }
}

extern "C" void kernel_launch(void* const* d_in, const int* in_sizes, int n_in,
                              void* d_out, int out_size)
{
    const float* tf  = (const float*)d_in[0];
    const float* sf  = (const float*)d_in[1];
    const float* Wq  = (const float*)d_in[2];
    const float* Wk  = (const float*)d_in[3];
    const float* Wv  = (const float*)d_in[4];
    const float* Wo  = (const float*)d_in[5];
    const float* lnw = (const float*)d_in[6];
    const float* lnb = (const float*)d_in[7];
    float* out = (float*)d_out;

    int B = in_sizes[0] / (CH * IMG_H * IMG_W);
    if (B < 1) B = 1;
    int n_windows = B * (IMG_H / WSZ) * (IMG_W / WSZ);

    dim3 pg(64, 4);
    prep_kernel<<<pg, 256>>>(Wq, Wk, Wv, Wo);

    cudaFuncSetAttribute(evsr_kernel, cudaFuncAttributeMaxDynamicSharedMemorySize,
                         SMEM_BYTES);
    evsr_kernel<<<n_windows, TPB, SMEM_BYTES>>>(tf, sf, lnw, lnb, out);
}

// round 14
// speedup vs baseline: 2.0259x; 1.1446x over previous
#include <cuda_runtime.h>
#include <cuda_fp16.h>
#include <mma.h>
#include <math.h>

using namespace nvcuda;
typedef unsigned int u32;

constexpr int TPB = 512;
constexpr int CH = 128, IMG_H = 256, IMG_W = 256, WSZ = 8;

// smem layout (bytes), total 216064
constexpr int OFF_LN = 0;       // 1024: lnw(128)+lnb(128) fp32
constexpr int WB0 = 1024;       // weight slab buf0 (20480) -> P probs in attention
constexpr int WB1 = 21504;      // weight slab buf1 (20480)
constexpr int XT  = 41984;      // X-temporal hi img (17408) -> AO hi img
constexpr int XS  = 59392;      // X-spatial hi img (17408)
constexpr int QH  = 76800;      // Q hi img
constexpr int QL  = 94208;      // Q lo img (3-term S)
constexpr int KH  = 111616;     // K hi img -> residual fp32 (spans KH+KL)
constexpr int KL  = 129024;     // K lo img
constexpr int VH  = 146432;     // V hi img
constexpr int VL  = 163840;     // V lo img
constexpr int F0  = 181248;     // fp32 [128][68] proj out / S / AO f32 / final
constexpr int SMEM_BYTES = 216064;
constexpr int RESID = KH;       // residual fp32 [t][128]

// prepped weights: plain row-major [m][d][c], fp16 hi and lo
__device__ __align__(16) half WH16[4 * 16384];
__device__ __align__(16) half WL16[4 * 16384];

__device__ __forceinline__ u32 smem_u32(const void* p) {
    u32 a;
    asm("{ .reg .u64 t; cvta.to.shared.u64 t, %1; cvt.u32.u64 %0, t; }"
        : "=r"(a) : "l"(p));
    return a;
}

__global__ void __launch_bounds__(256) prep_kernel(
    const float* __restrict__ Wq, const float* __restrict__ Wk,
    const float* __restrict__ Wv, const float* __restrict__ Wo)
{
    int m = blockIdx.y;
    const float* Ws = (m == 0) ? Wq : (m == 1) ? Wk : (m == 2) ? Wv : Wo;
    int idx = blockIdx.x * 256 + threadIdx.x;
    float v = Ws[idx];
    half h = __float2half_rn(v);
    WH16[m * 16384 + idx] = h;
    WL16[m * 16384 + idx] = __float2half_rn(v - __half2float(h));
}

typedef wmma::fragment<wmma::matrix_a, 16, 16, 16, half, wmma::row_major> FA;
typedef wmma::fragment<wmma::matrix_b, 16, 16, 16, half, wmma::col_major> FBc;
typedef wmma::fragment<wmma::matrix_b, 16, 16, 16, half, wmma::row_major> FBr;
typedef wmma::fragment<wmma::accumulator, 16, 16, 16, float> FC;

// async copy of one weight slab i (proj i>>2, k-slab i&3) into buffer
__device__ __forceinline__ void cp_slab(u32 sb, int bufoff, int i, int tid) {
    int proj = i >> 2, s = i & 3;
    const char* WH = (const char*)WH16 + proj * 32768;
    const char* WL = (const char*)WL16 + proj * 32768;
    int d = tid >> 2, cp = tid & 3;
    u32 dst = sb + bufoff + d * 80 + cp * 16;
    const char* srcH = WH + d * 256 + s * 64 + cp * 16;
    const char* srcL = WL + d * 256 + s * 64 + cp * 16;
    asm volatile("cp.async.cg.shared.global [%0], [%1], 16;" :: "r"(dst), "l"(srcH));
    asm volatile("cp.async.cg.shared.global [%0], [%1], 16;" :: "r"(dst + 10240), "l"(srcL));
    asm volatile("cp.async.commit_group;" ::: "memory");
}
__device__ __forceinline__ void cp_wait0() {
    asm volatile("cp.async.wait_group 0;" ::: "memory");
}

// one k-slab (32 cols, 2 k-tiles) of the projection: acc += (Wh+Wl) * Xh^T
__device__ __forceinline__ void comp_slab(char* smem, int bufoff, int s,
                                          const half* Bimg, FC* acc,
                                          int mt, int np)
{
    const half* Ah = (const half*)(smem + bufoff) + mt * 16 * 40;
    const half* Al = (const half*)(smem + bufoff + 10240) + mt * 16 * 40;
#pragma unroll
    for (int kt = 0; kt < 2; kt++) {
        FA ah, al;
        wmma::load_matrix_sync(ah, Ah + kt * 16, 40);
        wmma::load_matrix_sync(al, Al + kt * 16, 40);
#pragma unroll
        for (int j = 0; j < 2; j++) {
            FBc b;
            wmma::load_matrix_sync(b, Bimg + (np * 2 + j) * 16 * 136 + s * 32 + kt * 16, 136);
            wmma::mma_sync(acc[j], ah, b, acc[j]);
            wmma::mma_sync(acc[j], al, b, acc[j]);
        }
    }
}

__global__ void __launch_bounds__(TPB, 1)
evsr_kernel(const float* __restrict__ tf, const float* __restrict__ sf,
            const float* __restrict__ lnw, const float* __restrict__ lnb,
            float* __restrict__ out)
{
    extern __shared__ char smem[];
    const int tid = threadIdx.x;
    const int w = tid >> 5;
    const int blk = blockIdx.x;
    const int b = blk >> 10, wy = (blk >> 5) & 31, wx = blk & 31;
    const int base = ((b * CH) << 16) + ((wy * WSZ) << 8) + (wx * WSZ);
    const u32 sb = smem_u32(smem);

    float* F0f = (float*)(smem + F0);
    float* LNF = (float*)(smem + OFF_LN);

    // ---- phase 0: start weight slab 0 copy, build X images ----
    cp_slab(sb, WB0, 0, tid);
    {
        half* XTi = (half*)(smem + XT);
        half* XSi = (half*)(smem + XS);
#pragma unroll
        for (int k = 0; k < 16; k++) {
            int idx = tid + k * TPB;
            int c = idx >> 6, t = idx & 63;
            int g = base + (c << 16) + ((t >> 3) << 8) + (t & 7);
            XTi[t * 136 + c] = __float2half_rn(tf[g]);
            XSi[t * 136 + c] = __float2half_rn(sf[g]);
        }
    }
    if (tid < 256) LNF[tid] = (tid < 128) ? lnw[tid] : lnb[tid - 128];
    cp_wait0();
    __syncthreads();

    const int mt = w >> 1, np = w & 1;
    const float scl = 0.17677669529663687f;

    // ---- projections Q,K,V: 12 pipelined slabs ----
    {
        FC acc[2];
        for (int i = 0; i < 12; i++) {
            if ((i & 3) == 0) {
                wmma::fill_fragment(acc[0], 0.0f);
                wmma::fill_fragment(acc[1], 0.0f);
            }
            if (i < 11) cp_slab(sb, ((i + 1) & 1) ? WB1 : WB0, i + 1, tid);
            const half* Bimg = (const half*)(smem + ((i >> 2) == 0 ? XT : XS));
            comp_slab(smem, (i & 1) ? WB1 : WB0, i & 3, Bimg, acc, mt, np);
            if ((i & 3) == 3) {
#pragma unroll
                for (int j = 0; j < 2; j++)
                    wmma::store_matrix_sync(F0f + mt * 16 * 68 + (np * 2 + j) * 16,
                                            acc[j], 68, wmma::mem_row_major);
            }
            cp_wait0();
            __syncthreads();

            if (i == 3) {        // epilogue Q: RoPE + scale -> QH/QL
#pragma unroll
                for (int k = 0; k < 8; k++) {
                    int idx = tid + k * TPB;
                    int i16 = idx & 15, h4 = (idx >> 4) & 3, t = idx >> 6;
                    float freq = exp2f(-(float)i16 * 0.830482023721841f);
                    float ang = (float)((t >> 3) + (t & 7)) * freq;
                    float sv, cv; __sincosf(ang, &sv, &cv);
                    int d1 = h4 * 32 + i16, d2 = d1 + 16;
                    float q1 = F0f[d1 * 68 + t], q2 = F0f[d2 * 68 + t];
                    float r1 = (q1 * cv - q2 * sv) * scl;
                    float r2 = (q1 * sv + q2 * cv) * scl;
                    half* Qh = (half*)(smem + QH);
                    half* Ql = (half*)(smem + QL);
                    half h1 = __float2half_rn(r1);
                    half h2 = __float2half_rn(r2);
                    Qh[t * 136 + d1] = h1;
                    Ql[t * 136 + d1] = __float2half_rn(r1 - __half2float(h1));
                    Qh[t * 136 + d2] = h2;
                    Ql[t * 136 + d2] = __float2half_rn(r2 - __half2float(h2));
                }
            } else if (i == 7) { // epilogue K: RoPE -> KH/KL
#pragma unroll
                for (int k = 0; k < 8; k++) {
                    int idx = tid + k * TPB;
                    int i16 = idx & 15, h4 = (idx >> 4) & 3, t = idx >> 6;
                    float freq = exp2f(-(float)i16 * 0.830482023721841f);
                    float ang = (float)((t >> 3) + (t & 7)) * freq;
                    float sv, cv; __sincosf(ang, &sv, &cv);
                    int d1 = h4 * 32 + i16, d2 = d1 + 16;
                    float k1 = F0f[d1 * 68 + t], k2 = F0f[d2 * 68 + t];
                    float r1 = k1 * cv - k2 * sv;
                    float r2 = k1 * sv + k2 * cv;
                    half* Kh = (half*)(smem + KH);
                    half* Kl = (half*)(smem + KL);
                    half h1 = __float2half_rn(r1);
                    half h2 = __float2half_rn(r2);
                    Kh[t * 136 + d1] = h1;
                    Kl[t * 136 + d1] = __float2half_rn(r1 - __half2float(h1));
                    Kh[t * 136 + d2] = h2;
                    Kl[t * 136 + d2] = __float2half_rn(r2 - __half2float(h2));
                }
            }
        }
    }
    // epilogue V -> VH/VL
    {
        half* Vh = (half*)(smem + VH);
        half* Vl = (half*)(smem + VL);
#pragma unroll
        for (int k = 0; k < 16; k++) {
            int idx = tid + k * TPB;
            int d = idx >> 6, t = idx & 63;
            float v = F0f[d * 68 + t];
            half h = __float2half_rn(v);
            Vh[t * 136 + d] = h;
            Vl[t * 136 + d] = __float2half_rn(v - __half2float(h));
        }
    }
    __syncthreads();

    // prefetch Wo slab0 into WB1 (WB0 becomes P during attention)
    cp_slab(sb, WB1, 12, tid);

    // ---- attention: 2 passes x 2 heads ----
    const int hl = w >> 3;
    const int amt = (w >> 1) & 3;
    const int an = w & 1;
    for (int p = 0; p < 2; p++) {
        const int head = 2 * p + hl;
        const int c0 = head * 32;

        {   // S = Q K^T (3-term), warp: 16 rows x 32 cols
            FC s2[2];
            wmma::fill_fragment(s2[0], 0.0f);
            wmma::fill_fragment(s2[1], 0.0f);
#pragma unroll
            for (int kt = 0; kt < 2; kt++) {
                FA qh, ql;
                wmma::load_matrix_sync(qh, (half*)(smem + QH) + amt * 16 * 136 + c0 + kt * 16, 136);
                wmma::load_matrix_sync(ql, (half*)(smem + QL) + amt * 16 * 136 + c0 + kt * 16, 136);
#pragma unroll
                for (int j = 0; j < 2; j++) {
                    int nt = an * 2 + j;
                    FBc kh, kl;
                    wmma::load_matrix_sync(kh, (half*)(smem + KH) + nt * 16 * 136 + c0 + kt * 16, 136);
                    wmma::load_matrix_sync(kl, (half*)(smem + KL) + nt * 16 * 136 + c0 + kt * 16, 136);
                    wmma::mma_sync(s2[j], qh, kh, s2[j]);
                    wmma::mma_sync(s2[j], qh, kl, s2[j]);
                    wmma::mma_sync(s2[j], ql, kh, s2[j]);
                }
            }
#pragma unroll
            for (int j = 0; j < 2; j++)
                wmma::store_matrix_sync(F0f + hl * 4352 + amt * 16 * 68 + (an * 2 + j) * 16,
                                        s2[j], 68, wmma::mem_row_major);
        }
        __syncthreads();

        {   // softmax (scale folded into Q), 4 threads per row
            int rid = tid >> 2, q4 = tid & 3;
            int h2 = rid >> 6, row = rid & 63;
            float* Srow = F0f + h2 * 4352 + row * 68 + q4 * 16;
            float mx = -1e30f;
#pragma unroll
            for (int j = 0; j < 16; j++) mx = fmaxf(mx, Srow[j]);
            mx = fmaxf(mx, __shfl_xor_sync(0xffffffffu, mx, 1, 4));
            mx = fmaxf(mx, __shfl_xor_sync(0xffffffffu, mx, 2, 4));
            float e[16], s = 0.0f;
#pragma unroll
            for (int j = 0; j < 16; j++) { e[j] = __expf(Srow[j] - mx); s += e[j]; }
            s += __shfl_xor_sync(0xffffffffu, s, 1, 4);
            s += __shfl_xor_sync(0xffffffffu, s, 2, 4);
            float inv = 1.0f / s;
            half* Pd = (half*)(smem + WB0) + h2 * 4608 + row * 72 + q4 * 16;
#pragma unroll
            for (int j = 0; j < 16; j++) Pd[j] = __float2half_rn(e[j] * inv);
        }
        __syncthreads();

        {   // O = P V (2-term), warp: 16 rows x 16 cols
            FC o;
            wmma::fill_fragment(o, 0.0f);
#pragma unroll
            for (int kt = 0; kt < 4; kt++) {
                FA ph;
                wmma::load_matrix_sync(ph, (half*)(smem + WB0) + hl * 4608 + amt * 16 * 72 + kt * 16, 72);
                FBr vh, vl;
                wmma::load_matrix_sync(vh, (half*)(smem + VH) + kt * 16 * 136 + c0 + an * 16, 136);
                wmma::load_matrix_sync(vl, (half*)(smem + VL) + kt * 16 * 136 + c0 + an * 16, 136);
                wmma::mma_sync(o, ph, vh, o);
                wmma::mma_sync(o, ph, vl, o);
            }
            wmma::store_matrix_sync(F0f + amt * 16 * 68 + hl * 32 + an * 16, o, 68,
                                    wmma::mem_row_major);
        }
        __syncthreads();

        // AO fp32 -> AO hi img (XT region), cols p*64..p*64+63
        {
            half* AOh = (half*)(smem + XT);
#pragma unroll
            for (int k = 0; k < 8; k++) {
                int idx = tid + k * TPB;
                int cc = idx & 63, t = idx >> 6;
                AOh[t * 136 + p * 64 + cc] = __float2half_rn(F0f[t * 68 + cc]);
            }
        }
        __syncthreads();
    }

    // residual reload (K region dead)
    {
        float* rF = (float*)(smem + RESID);
#pragma unroll
        for (int k = 0; k < 16; k++) {
            int idx = tid + k * TPB;
            int c = idx >> 6, t = idx & 63;
            rF[t * 128 + c] = tf[base + (c << 16) + ((t >> 3) << 8) + (t & 7)];
        }
    }

    // ---- O projection: 4 slabs, buffers parity-flipped (12->WB1) ----
    cp_wait0();
    __syncthreads();
    {
        FC acc[2];
        wmma::fill_fragment(acc[0], 0.0f);
        wmma::fill_fragment(acc[1], 0.0f);
        const half* Bimg = (const half*)(smem + XT);   // AO hi image
        for (int i = 12; i < 16; i++) {
            if (i < 15) cp_slab(sb, (((i + 1) & 1) ^ 1) ? WB1 : WB0, i + 1, tid);
            comp_slab(smem, (((i & 1) ^ 1)) ? WB1 : WB0, i & 3, Bimg, acc, mt, np);
            if (i == 15) {
#pragma unroll
                for (int j = 0; j < 2; j++)
                    wmma::store_matrix_sync(F0f + mt * 16 * 68 + (np * 2 + j) * 16,
                                            acc[j], 68, wmma::mem_row_major);
            }
            cp_wait0();
            __syncthreads();
        }
    }

    // ---- LayerNorm + residual (in place in F0, [d][t]) ----
    {
        int t = tid >> 3, j = tid & 7;
        const float* rF = (const float*)(smem + RESID);
        float s1 = 0.0f, s2 = 0.0f;
#pragma unroll
        for (int i = 0; i < 16; i++) {
            float v = F0f[(j * 16 + i) * 68 + t];
            s1 += v; s2 += v * v;
        }
#pragma unroll
        for (int d2 = 1; d2 < 8; d2 <<= 1) {
            s1 += __shfl_xor_sync(0xffffffffu, s1, d2, 8);
            s2 += __shfl_xor_sync(0xffffffffu, s2, d2, 8);
        }
        float mu = s1 * (1.0f / 128.0f);
        float var = s2 * (1.0f / 128.0f) - mu * mu;
        float inv = rsqrtf(var + 1e-5f);
#pragma unroll
        for (int i = 0; i < 16; i++) {
            int d = j * 16 + i;
            float v = F0f[d * 68 + t];
            F0f[d * 68 + t] = (v - mu) * inv * LNF[d] + LNF[128 + d] + rF[t * 128 + d];
        }
    }
    __syncthreads();

    // ---- store ----
#pragma unroll
    for (int k = 0; k < 16; k++) {
        int idx = tid + k * TPB;
        int c = idx >> 6, t = idx & 63;
        out[base + (c << 16) + ((t >> 3) << 8) + (t & 7)] = F0f[c * 68 + t];
    }
}

extern "C" void kernel_launch(void* const* d_in, const int* in_sizes, int n_in,
                              void* d_out, int out_size)
{
    const float* tf  = (const float*)d_in[0];
    const float* sf  = (const float*)d_in[1];
    const float* Wq  = (const float*)d_in[2];
    const float* Wk  = (const float*)d_in[3];
    const float* Wv  = (const float*)d_in[4];
    const float* Wo  = (const float*)d_in[5];
    const float* lnw = (const float*)d_in[6];
    const float* lnb = (const float*)d_in[7];
    float* out = (float*)d_out;

    int B = in_sizes[0] / (CH * IMG_H * IMG_W);
    if (B < 1) B = 1;
    int n_windows = B * (IMG_H / WSZ) * (IMG_W / WSZ);

    dim3 pg(64, 4);
    prep_kernel<<<pg, 256>>>(Wq, Wk, Wv, Wo);

    cudaFuncSetAttribute(evsr_kernel, cudaFuncAttributeMaxDynamicSharedMemorySize,
                         SMEM_BYTES);
    evsr_kernel<<<n_windows, TPB, SMEM_BYTES>>>(tf, sf, lnw, lnb, out);
}

// round 16
// speedup vs baseline: 2.4075x; 1.1884x over previous
#include <cuda_runtime.h>
#include <cuda_fp16.h>
#include <mma.h>
#include <math.h>

using namespace nvcuda;
typedef unsigned int u32;

constexpr int TPB = 512;
constexpr int CH = 128, IMG_H = 256, IMG_W = 256, WSZ = 8;

// smem layout (bytes), total 198656
constexpr int OFF_LN = 0;       // 1024
constexpr int WB0 = 1024;       // weight buf0 (20480); P probs (heads 0-1) in attn
constexpr int WB1 = 21504;      // weight buf1 (20480); P probs (heads 2-3)
constexpr int XT  = 41984;      // X-temporal img (17408) -> AO img for Wo
constexpr int XS  = 59392;      // X-spatial img (17408)
constexpr int QH  = 76800;      // Q img -> residual fp32 (spans QH..QH+32768)
constexpr int KH  = 94208;      // K img
constexpr int VH  = 111616;     // V img
constexpr int SB  = 129024;     // 69632: F0 proj-out fp32 / S fp32 (4 heads) / AO fp32 / final
constexpr int SMEM_BYTES = 198656;
constexpr int RESID = QH;       // residual fp32 [t][128] (32768 B)

// prepped weights: plain row-major [m][d][c], fp16 hi and lo
__device__ __align__(16) half WH16[4 * 16384];
__device__ __align__(16) half WL16[4 * 16384];

__device__ __forceinline__ u32 smem_u32(const void* p) {
    u32 a;
    asm("{ .reg .u64 t; cvta.to.shared.u64 t, %1; cvt.u32.u64 %0, t; }"
        : "=r"(a) : "l"(p));
    return a;
}

__global__ void __launch_bounds__(256) prep_kernel(
    const float* __restrict__ Wq, const float* __restrict__ Wk,
    const float* __restrict__ Wv, const float* __restrict__ Wo)
{
    int m = blockIdx.y;
    const float* Ws = (m == 0) ? Wq : (m == 1) ? Wk : (m == 2) ? Wv : Wo;
    int idx = blockIdx.x * 256 + threadIdx.x;
    float v = Ws[idx];
    half h = __float2half_rn(v);
    WH16[m * 16384 + idx] = h;
    WL16[m * 16384 + idx] = __float2half_rn(v - __half2float(h));
}

typedef wmma::fragment<wmma::matrix_a, 16, 16, 16, half, wmma::row_major> FA;
typedef wmma::fragment<wmma::matrix_b, 16, 16, 16, half, wmma::col_major> FBc;
typedef wmma::fragment<wmma::matrix_b, 16, 16, 16, half, wmma::row_major> FBr;
typedef wmma::fragment<wmma::accumulator, 16, 16, 16, float> FC;

// async copy of weight slab i (proj i>>2, k-slab i&3); lo plane optional
__device__ __forceinline__ void cp_slab(u32 sb, int bufoff, int i, int tid, bool lo) {
    int proj = i >> 2, s = i & 3;
    int d = tid >> 2, cp = tid & 3;
    u32 dst = sb + bufoff + d * 80 + cp * 16;
    const char* srcH = (const char*)WH16 + proj * 32768 + d * 256 + s * 64 + cp * 16;
    asm volatile("cp.async.cg.shared.global [%0], [%1], 16;" :: "r"(dst), "l"(srcH));
    if (lo) {
        const char* srcL = (const char*)WL16 + proj * 32768 + d * 256 + s * 64 + cp * 16;
        asm volatile("cp.async.cg.shared.global [%0], [%1], 16;" :: "r"(dst + 10240), "l"(srcL));
    }
    asm volatile("cp.async.commit_group;" ::: "memory");
}
__device__ __forceinline__ void cp_wait0() {
    asm volatile("cp.async.wait_group 0;" ::: "memory");
}

// one 32-col k-slab of a projection: acc += Wh * X^T (+ Wl * X^T if 2-term)
__device__ __forceinline__ void comp_slab(char* smem, int bufoff, int s,
                                          const half* Bimg, FC* acc,
                                          int mt, int np, int nterms)
{
    const half* Ah = (const half*)(smem + bufoff) + mt * 16 * 40;
    const half* Al = (const half*)(smem + bufoff + 10240) + mt * 16 * 40;
#pragma unroll
    for (int kt = 0; kt < 2; kt++) {
        FA ah;
        wmma::load_matrix_sync(ah, Ah + kt * 16, 40);
        FA al;
        if (nterms == 2) wmma::load_matrix_sync(al, Al + kt * 16, 40);
#pragma unroll
        for (int j = 0; j < 2; j++) {
            FBc b;
            wmma::load_matrix_sync(b, Bimg + (np * 2 + j) * 16 * 136 + s * 32 + kt * 16, 136);
            wmma::mma_sync(acc[j], ah, b, acc[j]);
            if (nterms == 2) wmma::mma_sync(acc[j], al, b, acc[j]);
        }
    }
}

__global__ void __launch_bounds__(TPB, 1)
evsr_kernel(const float* __restrict__ tf, const float* __restrict__ sf,
            const float* __restrict__ lnw, const float* __restrict__ lnb,
            float* __restrict__ out)
{
    extern __shared__ char smem[];
    const int tid = threadIdx.x;
    const int w = tid >> 5;
    const int blk = blockIdx.x;
    const int b = blk >> 10, wy = (blk >> 5) & 31, wx = blk & 31;
    const int base = ((b * CH) << 16) + ((wy * WSZ) << 8) + (wx * WSZ);
    const u32 sb = smem_u32(smem);

    float* F0f = (float*)(smem + SB);
    float* LNF = (float*)(smem + OFF_LN);

    // ---- phase 0: start Q slab0 copy; build X images ----
    cp_slab(sb, WB0, 0, tid, false);
    {
        half* XTi = (half*)(smem + XT);
        half* XSi = (half*)(smem + XS);
#pragma unroll
        for (int k = 0; k < 16; k++) {
            int idx = tid + k * TPB;
            int c = idx >> 6, t = idx & 63;
            int g = base + (c << 16) + ((t >> 3) << 8) + (t & 7);
            XTi[t * 136 + c] = __float2half_rn(tf[g]);
            XSi[t * 136 + c] = __float2half_rn(sf[g]);
        }
    }
    if (tid < 256) LNF[tid] = (tid < 128) ? lnw[tid] : lnb[tid - 128];
    cp_wait0();
    __syncthreads();

    const int mt = w >> 1, np = w & 1;
    const float scl = 0.17677669529663687f;

    // ---- projections Q(1-term), K(1-term), V(2-term): 12 pipelined slabs ----
    {
        FC acc[2];
        for (int i = 0; i < 12; i++) {
            if ((i & 3) == 0) {
                wmma::fill_fragment(acc[0], 0.0f);
                wmma::fill_fragment(acc[1], 0.0f);
            }
            if (i < 11) cp_slab(sb, ((i + 1) & 1) ? WB1 : WB0, i + 1, tid, (i + 1) >= 8);
            const half* Bimg = (const half*)(smem + ((i >> 2) == 0 ? XT : XS));
            comp_slab(smem, (i & 1) ? WB1 : WB0, i & 3, Bimg, acc, mt, np,
                      (i >= 8) ? 2 : 1);
            if ((i & 3) == 3) {
#pragma unroll
                for (int j = 0; j < 2; j++)
                    wmma::store_matrix_sync(F0f + mt * 16 * 68 + (np * 2 + j) * 16,
                                            acc[j], 68, wmma::mem_row_major);
            }
            cp_wait0();
            __syncthreads();

            if (i == 3) {        // epilogue Q: RoPE + scale -> QH
                half* Qi = (half*)(smem + QH);
#pragma unroll
                for (int k = 0; k < 8; k++) {
                    int idx = tid + k * TPB;
                    int i16 = idx & 15, h4 = (idx >> 4) & 3, t = idx >> 6;
                    float freq = exp2f(-(float)i16 * 0.830482023721841f);
                    float ang = (float)((t >> 3) + (t & 7)) * freq;
                    float sv, cv; __sincosf(ang, &sv, &cv);
                    int d1 = h4 * 32 + i16, d2 = d1 + 16;
                    float q1 = F0f[d1 * 68 + t], q2 = F0f[d2 * 68 + t];
                    Qi[t * 136 + d1] = __float2half_rn((q1 * cv - q2 * sv) * scl);
                    Qi[t * 136 + d2] = __float2half_rn((q1 * sv + q2 * cv) * scl);
                }
            } else if (i == 7) { // epilogue K: RoPE -> KH
                half* Ki = (half*)(smem + KH);
#pragma unroll
                for (int k = 0; k < 8; k++) {
                    int idx = tid + k * TPB;
                    int i16 = idx & 15, h4 = (idx >> 4) & 3, t = idx >> 6;
                    float freq = exp2f(-(float)i16 * 0.830482023721841f);
                    float ang = (float)((t >> 3) + (t & 7)) * freq;
                    float sv, cv; __sincosf(ang, &sv, &cv);
                    int d1 = h4 * 32 + i16, d2 = d1 + 16;
                    float k1 = F0f[d1 * 68 + t], k2 = F0f[d2 * 68 + t];
                    Ki[t * 136 + d1] = __float2half_rn(k1 * cv - k2 * sv);
                    Ki[t * 136 + d2] = __float2half_rn(k1 * sv + k2 * cv);
                }
            }
        }
    }
    // epilogue V -> VH
    {
        half* Vi = (half*)(smem + VH);
#pragma unroll
        for (int k = 0; k < 16; k++) {
            int idx = tid + k * TPB;
            int d = idx >> 6, t = idx & 63;
            Vi[t * 136 + d] = __float2half_rn(F0f[d * 68 + t]);
        }
    }
    __syncthreads();   // V epilogue reads F0 before S overwrites SB region

    // ---- attention: single pass, all 4 heads ----
    const int ahead = w >> 2, amt = w & 3;
    float* SBf = (float*)(smem + SB);

    {   // S = Q K^T : warp = (head, 16-row tile), full 64 cols
        FC sacc[4];
#pragma unroll
        for (int j = 0; j < 4; j++) wmma::fill_fragment(sacc[j], 0.0f);
        const half* Qi = (const half*)(smem + QH);
        const half* Ki = (const half*)(smem + KH);
#pragma unroll
        for (int kt = 0; kt < 2; kt++) {
            FA qa;
            wmma::load_matrix_sync(qa, Qi + (amt * 16) * 136 + ahead * 32 + kt * 16, 136);
#pragma unroll
            for (int nt = 0; nt < 4; nt++) {
                FBc kb;
                wmma::load_matrix_sync(kb, Ki + (nt * 16) * 136 + ahead * 32 + kt * 16, 136);
                wmma::mma_sync(sacc[nt], qa, kb, sacc[nt]);
            }
        }
#pragma unroll
        for (int nt = 0; nt < 4; nt++)
            wmma::store_matrix_sync(SBf + ahead * 4352 + (amt * 16) * 68 + nt * 16,
                                    sacc[nt], 68, wmma::mem_row_major);
    }
    __syncthreads();

    {   // softmax: 2 threads per row, 256 rows
        int rid = tid >> 1, hf = tid & 1;
        int head = rid >> 6, row = rid & 63;
        float* Srow = SBf + head * 4352 + row * 68 + hf * 32;
        float mx = -1e30f;
#pragma unroll
        for (int j = 0; j < 32; j++) mx = fmaxf(mx, Srow[j]);
        mx = fmaxf(mx, __shfl_xor_sync(0xffffffffu, mx, 1));
        float e[32], s = 0.0f;
#pragma unroll
        for (int j = 0; j < 32; j++) { e[j] = __expf(Srow[j] - mx); s += e[j]; }
        s += __shfl_xor_sync(0xffffffffu, s, 1);
        float inv = 1.0f / s;
        half* Pd = (half*)(smem + WB0) + head * 4608 + row * 72 + hf * 32;
#pragma unroll
        for (int j = 0; j < 32; j++) Pd[j] = __float2half_rn(e[j] * inv);
    }
    __syncthreads();

    {   // O = P V : warp = (head, 16-row tile), 32 cols -> AO fp32 (SB region)
        FC oacc[2];
        wmma::fill_fragment(oacc[0], 0.0f);
        wmma::fill_fragment(oacc[1], 0.0f);
        const half* Pi = (const half*)(smem + WB0) + ahead * 4608;
        const half* Vi = (const half*)(smem + VH);
        float* AOf = (float*)(smem + SB);
#pragma unroll
        for (int kt = 0; kt < 4; kt++) {
            FA pa;
            wmma::load_matrix_sync(pa, Pi + (amt * 16) * 72 + kt * 16, 72);
#pragma unroll
            for (int j = 0; j < 2; j++) {
                FBr vb;
                wmma::load_matrix_sync(vb, Vi + (kt * 16) * 136 + ahead * 32 + j * 16, 136);
                wmma::mma_sync(oacc[j], pa, vb, oacc[j]);
            }
        }
#pragma unroll
        for (int j = 0; j < 2; j++)
            wmma::store_matrix_sync(AOf + (amt * 16) * 132 + ahead * 32 + j * 16,
                                    oacc[j], 132, wmma::mem_row_major);
    }
    __syncthreads();

    // AO fp32 -> AO img (XT region)
    {
        half* AOi = (half*)(smem + XT);
        const float* AOf = (const float*)(smem + SB);
#pragma unroll
        for (int k = 0; k < 16; k++) {
            int idx = tid + k * TPB;
            int c = idx & 127, t = idx >> 7;
            AOi[t * 136 + c] = __float2half_rn(AOf[t * 132 + c]);
        }
    }
    __syncthreads();

    // ---- Wo: start staging; reload residual (QH region dead) ----
    cp_slab(sb, WB0, 12, tid, true);
    {
        float* rF = (float*)(smem + RESID);
#pragma unroll
        for (int k = 0; k < 16; k++) {
            int idx = tid + k * TPB;
            int c = idx >> 6, t = idx & 63;
            rF[t * 128 + c] = tf[base + (c << 16) + ((t >> 3) << 8) + (t & 7)];
        }
    }
    cp_wait0();
    __syncthreads();

    {   // Wo projection (2-term), 4 slabs
        FC acc[2];
        wmma::fill_fragment(acc[0], 0.0f);
        wmma::fill_fragment(acc[1], 0.0f);
        const half* Bimg = (const half*)(smem + XT);
        for (int i = 12; i < 16; i++) {
            if (i < 15) cp_slab(sb, ((i + 1) & 1) ? WB1 : WB0, i + 1, tid, true);
            comp_slab(smem, (i & 1) ? WB1 : WB0, i & 3, Bimg, acc, mt, np, 2);
            if (i == 15) {
#pragma unroll
                for (int j = 0; j < 2; j++)
                    wmma::store_matrix_sync(F0f + mt * 16 * 68 + (np * 2 + j) * 16,
                                            acc[j], 68, wmma::mem_row_major);
            }
            cp_wait0();
            __syncthreads();
        }
    }

    // ---- LayerNorm + residual (F0 [d][68], resid [t][128]) ----
    {
        int t = tid >> 3, j = tid & 7;
        const float* rF = (const float*)(smem + RESID);
        float s1 = 0.0f, s2 = 0.0f;
#pragma unroll
        for (int i = 0; i < 16; i++) {
            float v = F0f[(j * 16 + i) * 68 + t];
            s1 += v; s2 += v * v;
        }
#pragma unroll
        for (int d2 = 1; d2 < 8; d2 <<= 1) {
            s1 += __shfl_xor_sync(0xffffffffu, s1, d2, 8);
            s2 += __shfl_xor_sync(0xffffffffu, s2, d2, 8);
        }
        float mu = s1 * (1.0f / 128.0f);
        float var = s2 * (1.0f / 128.0f) - mu * mu;
        float inv = rsqrtf(var + 1e-5f);
#pragma unroll
        for (int i = 0; i < 16; i++) {
            int d = j * 16 + i;
            float v = F0f[d * 68 + t];
            F0f[d * 68 + t] = (v - mu) * inv * LNF[d] + LNF[128 + d] + rF[t * 128 + d];
        }
    }
    __syncthreads();

    // ---- store ----
#pragma unroll
    for (int k = 0; k < 16; k++) {
        int idx = tid + k * TPB;
        int c = idx >> 6, t = idx & 63;
        out[base + (c << 16) + ((t >> 3) << 8) + (t & 7)] = F0f[c * 68 + t];
    }
}

extern "C" void kernel_launch(void* const* d_in, const int* in_sizes, int n_in,
                              void* d_out, int out_size)
{
    const float* tf  = (const float*)d_in[0];
    const float* sf  = (const float*)d_in[1];
    const float* Wq  = (const float*)d_in[2];
    const float* Wk  = (const float*)d_in[3];
    const float* Wv  = (const float*)d_in[4];
    const float* Wo  = (const float*)d_in[5];
    const float* lnw = (const float*)d_in[6];
    const float* lnb = (const float*)d_in[7];
    float* out = (float*)d_out;

    int B = in_sizes[0] / (CH * IMG_H * IMG_W);
    if (B < 1) B = 1;
    int n_windows = B * (IMG_H / WSZ) * (IMG_W / WSZ);

    dim3 pg(64, 4);
    prep_kernel<<<pg, 256>>>(Wq, Wk, Wv, Wo);

    cudaFuncSetAttribute(evsr_kernel, cudaFuncAttributeMaxDynamicSharedMemorySize,
                         SMEM_BYTES);
    evsr_kernel<<<n_windows, TPB, SMEM_BYTES>>>(tf, sf, lnw, lnb, out);
}